// round 2
// baseline (speedup 1.0000x reference)
#include <cuda_runtime.h>
#include <math.h>

#define NN 10000
#define NE 256000
#define HH 128
#define H2 256
#define H3 384
#define NR 20

typedef unsigned long long u64;

// ---------------- scratch (static device globals; no allocation) ----------------
__device__ float g_x[NN * H3];
__device__ float g_filters[(size_t)NE * H3];
__device__ float g_qmid[NN * HH];
__device__ float g_mumid[NN * 3 * HH];
__device__ float g_vnorm[NN * HH];
__device__ float g_inner[NN * HH];
__device__ float g_muw[NN * 3 * HH];
__device__ int   g_count[NN];
__device__ int   g_off[NN + 1];
__device__ int   g_cursor[NN];
__device__ int   g_elist[NE];

__device__ __forceinline__ float silu_f(float x) {
    return x / (1.0f + __expf(-x));
}

// ---- packed f32x2 helpers ----
__device__ __forceinline__ u64 ffma2(u64 a, u64 b, u64 c) {
    u64 d;
    asm("fma.rn.f32x2 %0, %1, %2, %3;" : "=l"(d) : "l"(a), "l"(b), "l"(c));
    return d;
}
__device__ __forceinline__ u64 pack2(float lo, float hi) {
    u64 r;
    asm("mov.b64 %0, {%1, %2};" : "=l"(r) : "f"(lo), "f"(hi));
    return r;
}
__device__ __forceinline__ void unpack2(u64 v, float& lo, float& hi) {
    asm("mov.b64 {%0, %1}, %2;" : "=f"(lo), "=f"(hi) : "l"(v));
}

// ---------------- CSR build ----------------
__global__ void k_zero() {
    int i = blockIdx.x * blockDim.x + threadIdx.x;
    if (i < NN) g_count[i] = 0;
}

__global__ void k_count(const int* __restrict__ ei) {
    for (int e = blockIdx.x * blockDim.x + threadIdx.x; e < NE;
         e += gridDim.x * blockDim.x)
        atomicAdd(&g_count[ei[e]], 1);
}

__global__ __launch_bounds__(1024) void k_scan() {
    __shared__ int ps[1024];
    int tid = threadIdx.x;
    const int CH = (NN + 1023) / 1024;
    int base = tid * CH;
    int s = 0;
    for (int j = 0; j < CH; ++j) {
        int idx = base + j;
        if (idx < NN) s += g_count[idx];
    }
    ps[tid] = s;
    __syncthreads();
    for (int off = 1; off < 1024; off <<= 1) {
        int v = 0;
        if (tid >= off) v = ps[tid - off];
        __syncthreads();
        ps[tid] += v;
        __syncthreads();
    }
    int run = ps[tid] - s;
    for (int j = 0; j < CH; ++j) {
        int idx = base + j;
        if (idx < NN) {
            g_off[idx] = run;
            g_cursor[idx] = run;
            run += g_count[idx];
        }
    }
    if (tid == 1023) g_off[NN] = ps[1023];
}

__global__ void k_fill(const int* __restrict__ ei) {
    for (int e = blockIdx.x * blockDim.x + threadIdx.x; e < NE;
         e += gridDim.x * blockDim.x) {
        int t = ei[e];
        int pos = atomicAdd(&g_cursor[t], 1);
        g_elist[pos] = e;
    }
}

// ---------------- node inter MLP (f32x2): x = silu(q@W1+b1)@W2+b2 ----------------
// 16 nodes/block, 256 threads, dynamic smem: sqd[16][256] dup + shd[16][768] dup = 64KB
#define NODE_SMEM (16 * 256 * 4 + 16 * 768 * 4)
__global__ __launch_bounds__(256) void k_node_mlp(
    const float* __restrict__ q,
    const float* __restrict__ W1, const float* __restrict__ b1,
    const float* __restrict__ W2, const float* __restrict__ b2)
{
    extern __shared__ float sm[];
    float* sqd = sm;                 // 16 x 256 (dup)
    float* shd = sm + 16 * 256;      // 16 x 768 (dup)
    int tid = threadIdx.x;
    int n0 = blockIdx.x * 16;

    for (int i = tid; i < 16 * HH; i += 256) {
        int r = i >> 7, c = i & 127;
        float v = q[(n0 + r) * HH + c];
        *(u64*)&sqd[r * 256 + 2 * c] = pack2(v, v);
    }
    __syncthreads();

    int rg = tid / 48;          // 0..3 (+ pad region)
    int cg = tid % 48;
    int r0 = rg * 4;
    int c0 = cg * 8;
    bool active = (tid < 192);

    // hidden = silu(q @ W1 + b1)   [16,384]
    if (active) {
        u64 acc[4][4] = {};
        for (int k = 0; k < HH; ++k) {
            ulonglong2 wa = *(const ulonglong2*)&W1[k * H3 + c0];
            ulonglong2 wb = *(const ulonglong2*)&W1[k * H3 + c0 + 4];
            #pragma unroll
            for (int i = 0; i < 4; ++i) {
                u64 s = *(const u64*)&sqd[(r0 + i) * 256 + 2 * k];
                acc[i][0] = ffma2(s, wa.x, acc[i][0]);
                acc[i][1] = ffma2(s, wa.y, acc[i][1]);
                acc[i][2] = ffma2(s, wb.x, acc[i][2]);
                acc[i][3] = ffma2(s, wb.y, acc[i][3]);
            }
        }
        #pragma unroll
        for (int i = 0; i < 4; ++i)
            #pragma unroll
            for (int j = 0; j < 4; ++j) {
                float lo, hi; unpack2(acc[i][j], lo, hi);
                float vlo = silu_f(lo + b1[c0 + 2 * j]);
                float vhi = silu_f(hi + b1[c0 + 2 * j + 1]);
                *(u64*)&shd[(r0 + i) * 768 + 2 * (c0 + 2 * j)]     = pack2(vlo, vlo);
                *(u64*)&shd[(r0 + i) * 768 + 2 * (c0 + 2 * j) + 2] = pack2(vhi, vhi);
            }
    }
    __syncthreads();

    // x = hidden @ W2 + b2
    if (active) {
        u64 acc[4][4] = {};
        for (int k = 0; k < H3; ++k) {
            ulonglong2 wa = *(const ulonglong2*)&W2[k * H3 + c0];
            ulonglong2 wb = *(const ulonglong2*)&W2[k * H3 + c0 + 4];
            #pragma unroll
            for (int i = 0; i < 4; ++i) {
                u64 s = *(const u64*)&shd[(r0 + i) * 768 + 2 * k];
                acc[i][0] = ffma2(s, wa.x, acc[i][0]);
                acc[i][1] = ffma2(s, wa.y, acc[i][1]);
                acc[i][2] = ffma2(s, wb.x, acc[i][2]);
                acc[i][3] = ffma2(s, wb.y, acc[i][3]);
            }
        }
        #pragma unroll
        for (int i = 0; i < 4; ++i) {
            float out[8];
            #pragma unroll
            for (int j = 0; j < 4; ++j) {
                float lo, hi; unpack2(acc[i][j], lo, hi);
                out[2 * j]     = lo + b2[c0 + 2 * j];
                out[2 * j + 1] = hi + b2[c0 + 2 * j + 1];
            }
            size_t base = (size_t)(n0 + r0 + i) * H3 + c0;
            *(float4*)&g_x[base]     = make_float4(out[0], out[1], out[2], out[3]);
            *(float4*)&g_x[base + 4] = make_float4(out[4], out[5], out[6], out[7]);
        }
    }
}

// ---------------- edge filter MLP (f32x2) ----------------
// 64 edges/block, 256 threads. smem: scut[64] + srbd[64][40] dup + shd[64][256] dup
#define EDGE_SMEM (64 * 4 + 64 * 40 * 4 + 64 * 256 * 4)
__global__ __launch_bounds__(256) void k_edge_filter(
    const float* __restrict__ rbf, const float* __restrict__ cut,
    const float* __restrict__ Wf1, const float* __restrict__ bf1,
    const float* __restrict__ Wf2, const float* __restrict__ bf2)
{
    extern __shared__ float sm[];
    float* scut = sm;                       // 64
    float* srbd = sm + 64;                  // 64 x 40 (dup)
    float* shd  = sm + 64 + 64 * 40;        // 64 x 256 (dup)
    int tid = threadIdx.x;
    int e0 = blockIdx.x * 64;

    for (int i = tid; i < 64 * NR; i += 256) {
        int r = i / NR, c = i % NR;
        float v = rbf[(e0 + r) * NR + c];
        *(u64*)&srbd[r * 40 + 2 * c] = pack2(v, v);
    }
    if (tid < 64) scut[tid] = cut[e0 + tid];
    __syncthreads();

    // phase 1: hidden[64][128] = silu(rbf@Wf1+bf1), dup into shd
    {
        int rg = tid >> 4;      // 16 row groups of 4
        int cg = tid & 15;      // 16 col groups of 8
        int r0 = rg * 4, c0 = cg * 8;
        u64 acc[4][4] = {};
        for (int k = 0; k < NR; ++k) {
            ulonglong2 wa = *(const ulonglong2*)&Wf1[k * HH + c0];
            ulonglong2 wb = *(const ulonglong2*)&Wf1[k * HH + c0 + 4];
            #pragma unroll
            for (int i = 0; i < 4; ++i) {
                u64 s = *(const u64*)&srbd[(r0 + i) * 40 + 2 * k];
                acc[i][0] = ffma2(s, wa.x, acc[i][0]);
                acc[i][1] = ffma2(s, wa.y, acc[i][1]);
                acc[i][2] = ffma2(s, wb.x, acc[i][2]);
                acc[i][3] = ffma2(s, wb.y, acc[i][3]);
            }
        }
        #pragma unroll
        for (int i = 0; i < 4; ++i)
            #pragma unroll
            for (int j = 0; j < 4; ++j) {
                float lo, hi; unpack2(acc[i][j], lo, hi);
                float vlo = silu_f(lo + bf1[c0 + 2 * j]);
                float vhi = silu_f(hi + bf1[c0 + 2 * j + 1]);
                *(u64*)&shd[(r0 + i) * 256 + 2 * (c0 + 2 * j)]     = pack2(vlo, vlo);
                *(u64*)&shd[(r0 + i) * 256 + 2 * (c0 + 2 * j) + 2] = pack2(vhi, vhi);
            }
    }
    __syncthreads();

    // phase 2: filters[64][384]
    #pragma unroll 1
    for (int pass = 0; pass < 3; ++pass) {
        int slot = pass * 256 + tid;
        int rg = slot / 48, cg = slot % 48;
        int r0 = rg * 4, c0 = cg * 8;
        u64 acc[4][4] = {};
        for (int k = 0; k < HH; ++k) {
            ulonglong2 wa = *(const ulonglong2*)&Wf2[k * H3 + c0];
            ulonglong2 wb = *(const ulonglong2*)&Wf2[k * H3 + c0 + 4];
            #pragma unroll
            for (int i = 0; i < 4; ++i) {
                u64 s = *(const u64*)&shd[(r0 + i) * 256 + 2 * k];
                acc[i][0] = ffma2(s, wa.x, acc[i][0]);
                acc[i][1] = ffma2(s, wa.y, acc[i][1]);
                acc[i][2] = ffma2(s, wb.x, acc[i][2]);
                acc[i][3] = ffma2(s, wb.y, acc[i][3]);
            }
        }
        #pragma unroll
        for (int i = 0; i < 4; ++i) {
            float c = scut[r0 + i];
            float out[8];
            #pragma unroll
            for (int j = 0; j < 4; ++j) {
                float lo, hi; unpack2(acc[i][j], lo, hi);
                out[2 * j]     = (lo + bf2[c0 + 2 * j]) * c;
                out[2 * j + 1] = (hi + bf2[c0 + 2 * j + 1]) * c;
            }
            size_t base = (size_t)(e0 + r0 + i) * H3 + c0;
            *(float4*)&g_filters[base]     = make_float4(out[0], out[1], out[2], out[3]);
            *(float4*)&g_filters[base + 4] = make_float4(out[4], out[5], out[6], out[7]);
        }
    }
}

// ---------------- pull aggregation (CSR) -> qmid, mumid ----------------
__global__ __launch_bounds__(128) void k_aggregate(
    const float* __restrict__ q, const float* __restrict__ mu,
    const int* __restrict__ ei, const float* __restrict__ uv)
{
    int n = blockIdx.x;
    int h = threadIdx.x;
    int beg = g_off[n], end = g_off[n + 1];
    float qa = 0.f, m0 = 0.f, m1 = 0.f, m2 = 0.f;
    for (int i = beg; i < end; ++i) {
        int e = g_elist[i];
        int s = ei[NE + e];
        const float* f = &g_filters[(size_t)e * H3];
        float fq = f[h], fr = f[HH + h], fm = f[2 * HH + h];
        const float* xs = &g_x[s * H3];
        float xq = xs[h] * fq;
        float xr = xs[HH + h] * fr;
        float xm = xs[2 * HH + h] * fm;
        float u0 = uv[e * 3 + 0], u1 = uv[e * 3 + 1], u2 = uv[e * 3 + 2];
        const float* ms = &mu[s * 3 * HH];
        qa += xq;
        m0 = fmaf(u0, xr, fmaf(ms[h],          xm, m0));
        m1 = fmaf(u1, xr, fmaf(ms[HH + h],     xm, m1));
        m2 = fmaf(u2, xr, fmaf(ms[2 * HH + h], xm, m2));
    }
    g_qmid[n * HH + h] = q[n * HH + h] + qa;
    g_mumid[n * 3 * HH + h]          = mu[n * 3 * HH + h] + m0;
    g_mumid[n * 3 * HH + HH + h]     = mu[n * 3 * HH + HH + h] + m1;
    g_mumid[n * 3 * HH + 2 * HH + h] = mu[n * 3 * HH + 2 * HH + h] + m2;
}

// ---------------- equivariant linear: vnorm, inner, mu_w ----------------
__global__ __launch_bounds__(256) void k_equiv(const float* __restrict__ Wvec)
{
    __shared__ float smu[24][3 * HH];
    int tid = threadIdx.x;
    int n0 = blockIdx.x * 24;

    for (int i = tid; i < 24 * 3 * HH; i += 256) {
        int r = i / (3 * HH);
        int c = i % (3 * HH);
        int n = n0 + r;
        smu[r][c] = (n < NN) ? g_mumid[n * 3 * HH + c] : 0.f;
    }
    __syncthreads();

    for (int slot = tid; slot < 6 * HH; slot += 256) {
        int ng = slot >> 7;
        int o  = slot & 127;
        int r0 = ng * 4;
        float v[4][3] = {};
        float w[4][3] = {};
        for (int k = 0; k < HH; ++k) {
            float wv = Wvec[k * H2 + o];
            float ww = Wvec[k * H2 + HH + o];
            #pragma unroll
            for (int i = 0; i < 4; ++i)
                #pragma unroll
                for (int d = 0; d < 3; ++d) {
                    float m = smu[r0 + i][d * HH + k];
                    v[i][d] = fmaf(m, wv, v[i][d]);
                    w[i][d] = fmaf(m, ww, w[i][d]);
                }
        }
        #pragma unroll
        for (int i = 0; i < 4; ++i) {
            int n = n0 + r0 + i;
            if (n >= NN) break;
            float vn = sqrtf(v[i][0] * v[i][0] + v[i][1] * v[i][1] +
                             v[i][2] * v[i][2] + 1e-8f);
            float in = v[i][0] * w[i][0] + v[i][1] * w[i][1] + v[i][2] * w[i][2];
            g_vnorm[n * HH + o] = vn;
            g_inner[n * HH + o] = in;
            g_muw[n * 3 * HH + o]          = w[i][0];
            g_muw[n * 3 * HH + HH + o]     = w[i][1];
            g_muw[n * 3 * HH + 2 * HH + o] = w[i][2];
        }
    }
}

// ---------------- scalar mix MLP + final update ----------------
// 16 nodes/block, 256 threads. dynamic smem: sind[16][512] dup + shid[16][384]
#define MIX_SMEM (16 * 512 * 4 + 16 * 384 * 4)
__global__ __launch_bounds__(256) void k_mix(
    const float* __restrict__ Wm1, const float* __restrict__ bm1,
    const float* __restrict__ Wm2, const float* __restrict__ bm2,
    float* __restrict__ qout, float* __restrict__ muout)
{
    extern __shared__ float sm[];
    float* sind = sm;                  // 16 x 512 (dup)
    float* shid = sm + 16 * 512;       // 16 x 384
    int tid = threadIdx.x;
    int n0 = blockIdx.x * 16;

    for (int i = tid; i < 16 * H2; i += 256) {
        int r = i >> 8;
        int c = i & 255;
        int n = n0 + r;
        float v = 0.f;
        if (n < NN) v = (c < HH) ? g_qmid[n * HH + c] : g_vnorm[n * HH + (c - HH)];
        *(u64*)&sind[r * 512 + 2 * c] = pack2(v, v);
    }
    __syncthreads();

    // hidden = silu(scalar_input @ Wm1 + bm1)   [16,384]
    if (tid < 192) {
        int rg = tid / 48;
        int cg = tid % 48;
        int r0 = rg * 4, c0 = cg * 8;
        u64 acc[4][4] = {};
        for (int k = 0; k < H2; ++k) {
            ulonglong2 wa = *(const ulonglong2*)&Wm1[k * H3 + c0];
            ulonglong2 wb = *(const ulonglong2*)&Wm1[k * H3 + c0 + 4];
            #pragma unroll
            for (int i = 0; i < 4; ++i) {
                u64 s = *(const u64*)&sind[(r0 + i) * 512 + 2 * k];
                acc[i][0] = ffma2(s, wa.x, acc[i][0]);
                acc[i][1] = ffma2(s, wa.y, acc[i][1]);
                acc[i][2] = ffma2(s, wb.x, acc[i][2]);
                acc[i][3] = ffma2(s, wb.y, acc[i][3]);
            }
        }
        #pragma unroll
        for (int i = 0; i < 4; ++i)
            #pragma unroll
            for (int j = 0; j < 4; ++j) {
                float lo, hi; unpack2(acc[i][j], lo, hi);
                shid[(r0 + i) * H3 + c0 + 2 * j]     = silu_f(lo + bm1[c0 + 2 * j]);
                shid[(r0 + i) * H3 + c0 + 2 * j + 1] = silu_f(hi + bm1[c0 + 2 * j + 1]);
            }
    }
    __syncthreads();

    // delta = hidden @ Wm2 + bm2, then final update
    for (int slot = tid; slot < 4 * HH; slot += 256) {
        int ng = slot >> 7;
        int o  = slot & 127;
        int rr0 = ng * 4;
        float aq[4] = {}, as[4] = {}, am[4] = {};
        for (int k = 0; k < H3; ++k) {
            float wq = Wm2[k * H3 + o];
            float ws = Wm2[k * H3 + HH + o];
            float wm = Wm2[k * H3 + 2 * HH + o];
            #pragma unroll
            for (int i = 0; i < 4; ++i) {
                float hv = shid[(rr0 + i) * H3 + k];
                aq[i] = fmaf(hv, wq, aq[i]);
                as[i] = fmaf(hv, ws, as[i]);
                am[i] = fmaf(hv, wm, am[i]);
            }
        }
        #pragma unroll
        for (int i = 0; i < 4; ++i) {
            int n = n0 + rr0 + i;
            if (n >= NN) break;
            float dq  = aq[i] + bm2[o];
            float dms = as[i] + bm2[HH + o];
            float dqm = am[i] + bm2[2 * HH + o];
            qout[n * HH + o] = g_qmid[n * HH + o] + dq + dqm * g_inner[n * HH + o];
            #pragma unroll
            for (int d = 0; d < 3; ++d) {
                int idx = n * 3 * HH + d * HH + o;
                muout[idx] = g_mumid[idx] + g_muw[idx] * dms;
            }
        }
    }
}

// ---------------- launch ----------------
extern "C" void kernel_launch(void* const* d_in, const int* in_sizes, int n_in,
                              void* d_out, int out_size)
{
    const float* q   = (const float*)d_in[0];
    const float* mu  = (const float*)d_in[1];
    const int*   ei  = (const int*)d_in[2];
    const float* rbf = (const float*)d_in[3];
    const float* uv  = (const float*)d_in[4];
    const float* cut = (const float*)d_in[5];
    const float* Wi1 = (const float*)d_in[6];
    const float* bi1 = (const float*)d_in[7];
    const float* Wi2 = (const float*)d_in[8];
    const float* bi2 = (const float*)d_in[9];
    const float* Wf1 = (const float*)d_in[10];
    const float* bf1 = (const float*)d_in[11];
    const float* Wf2 = (const float*)d_in[12];
    const float* bf2 = (const float*)d_in[13];
    const float* Wv  = (const float*)d_in[14];
    const float* Wm1 = (const float*)d_in[15];
    const float* bm1 = (const float*)d_in[16];
    const float* Wm2 = (const float*)d_in[17];
    const float* bm2 = (const float*)d_in[18];

    float* qout  = (float*)d_out;
    float* muout = qout + (size_t)NN * HH;

    cudaFuncSetAttribute(k_edge_filter, cudaFuncAttributeMaxDynamicSharedMemorySize, EDGE_SMEM);
    cudaFuncSetAttribute(k_node_mlp,    cudaFuncAttributeMaxDynamicSharedMemorySize, NODE_SMEM);
    cudaFuncSetAttribute(k_mix,         cudaFuncAttributeMaxDynamicSharedMemorySize, MIX_SMEM);

    // CSR build
    k_zero<<<(NN + 255) / 256, 256>>>();
    k_count<<<512, 256>>>(ei);
    k_scan<<<1, 1024>>>();
    k_fill<<<512, 256>>>(ei);

    // dense stages
    k_node_mlp<<<NN / 16, 256, NODE_SMEM>>>(q, Wi1, bi1, Wi2, bi2);
    k_edge_filter<<<NE / 64, 256, EDGE_SMEM>>>(rbf, cut, Wf1, bf1, Wf2, bf2);

    // message aggregation
    k_aggregate<<<NN, 128>>>(q, mu, ei, uv);

    // mixing
    k_equiv<<<(NN + 23) / 24, 256>>>(Wv);
    k_mix<<<(NN + 15) / 16, 256, MIX_SMEM>>>(Wm1, bm1, Wm2, bm2, qout, muout);
}

// round 3
// speedup vs baseline: 1.1676x; 1.1676x over previous
#include <cuda_runtime.h>
#include <math.h>

#define NN 10000
#define NE 256000
#define HH 128
#define H2 256
#define H3 384
#define NR 20

typedef unsigned long long u64;

// ---------------- scratch (static device globals; no allocation) ----------------
__device__ float g_x[NN * H3];
__device__ float g_filters[(size_t)NE * H3];
__device__ float g_wdup[HH * 2 * H3];          // Wf2 with each column duplicated
__device__ float g_qmid[NN * HH];
__device__ float g_mumid[NN * 3 * HH];
__device__ float g_vnorm[NN * HH];
__device__ float g_inner[NN * HH];
__device__ float g_muw[NN * 3 * HH];
__device__ int   g_count[NN];
__device__ int   g_off[NN + 1];
__device__ int   g_cursor[NN];
__device__ int   g_elist[NE];

__device__ __forceinline__ float silu_f(float x) {
    return x / (1.0f + __expf(-x));
}

__device__ __forceinline__ u64 ffma2(u64 a, u64 b, u64 c) {
    u64 d;
    asm("fma.rn.f32x2 %0, %1, %2, %3;" : "=l"(d) : "l"(a), "l"(b), "l"(c));
    return d;
}
__device__ __forceinline__ void unpack2(u64 v, float& lo, float& hi) {
    asm("mov.b64 {%0, %1}, %2;" : "=f"(lo), "=f"(hi) : "l"(v));
}

// ---------------- weight duplication (one-shot, tiny) ----------------
__global__ void k_dupw(const float* __restrict__ Wf2) {
    int i = blockIdx.x * blockDim.x + threadIdx.x;   // over HH*H3
    if (i < HH * H3) {
        int k = i / H3, c = i % H3;
        float w = Wf2[i];
        g_wdup[k * 2 * H3 + 2 * c]     = w;
        g_wdup[k * 2 * H3 + 2 * c + 1] = w;
    }
}

// ---------------- CSR build ----------------
__global__ void k_zero() {
    int i = blockIdx.x * blockDim.x + threadIdx.x;
    if (i < NN) g_count[i] = 0;
}

__global__ void k_count(const int* __restrict__ ei) {
    for (int e = blockIdx.x * blockDim.x + threadIdx.x; e < NE;
         e += gridDim.x * blockDim.x)
        atomicAdd(&g_count[ei[e]], 1);
}

__global__ __launch_bounds__(1024) void k_scan() {
    __shared__ int ps[1024];
    int tid = threadIdx.x;
    const int CH = (NN + 1023) / 1024;
    int base = tid * CH;
    int s = 0;
    for (int j = 0; j < CH; ++j) {
        int idx = base + j;
        if (idx < NN) s += g_count[idx];
    }
    ps[tid] = s;
    __syncthreads();
    for (int off = 1; off < 1024; off <<= 1) {
        int v = 0;
        if (tid >= off) v = ps[tid - off];
        __syncthreads();
        ps[tid] += v;
        __syncthreads();
    }
    int run = ps[tid] - s;
    for (int j = 0; j < CH; ++j) {
        int idx = base + j;
        if (idx < NN) {
            g_off[idx] = run;
            g_cursor[idx] = run;
            run += g_count[idx];
        }
    }
    if (tid == 1023) g_off[NN] = ps[1023];
}

__global__ void k_fill(const int* __restrict__ ei) {
    for (int e = blockIdx.x * blockDim.x + threadIdx.x; e < NE;
         e += gridDim.x * blockDim.x) {
        int t = ei[e];
        int pos = atomicAdd(&g_cursor[t], 1);
        g_elist[pos] = e;
    }
}

// ---------------- node inter MLP (Round-1 proven version) ----------------
__global__ __launch_bounds__(256) void k_node_mlp(
    const float* __restrict__ q,
    const float* __restrict__ W1, const float* __restrict__ b1,
    const float* __restrict__ W2, const float* __restrict__ b2)
{
    __shared__ float sq[16][HH];
    __shared__ float sh[16][H3];
    int tid = threadIdx.x;
    int n0 = blockIdx.x * 16;

    for (int i = tid; i < 16 * HH; i += 256)
        sq[i / HH][i % HH] = q[(n0 + i / HH) * HH + (i % HH)];
    __syncthreads();

    int rg = tid >> 6;
    int cg = tid & 63;
    int r0 = rg * 4;

    for (int pass = 0; pass < 2; ++pass) {
        int c0 = cg * 4 + pass * 256;
        if (c0 >= H3) break;
        float acc[4][4] = {};
        for (int k = 0; k < HH; ++k) {
            float4 w = *reinterpret_cast<const float4*>(&W1[k * H3 + c0]);
            #pragma unroll
            for (int i = 0; i < 4; ++i) {
                float s = sq[r0 + i][k];
                acc[i][0] = fmaf(s, w.x, acc[i][0]);
                acc[i][1] = fmaf(s, w.y, acc[i][1]);
                acc[i][2] = fmaf(s, w.z, acc[i][2]);
                acc[i][3] = fmaf(s, w.w, acc[i][3]);
            }
        }
        #pragma unroll
        for (int i = 0; i < 4; ++i)
            #pragma unroll
            for (int j = 0; j < 4; ++j)
                sh[r0 + i][c0 + j] = silu_f(acc[i][j] + b1[c0 + j]);
    }
    __syncthreads();

    for (int pass = 0; pass < 2; ++pass) {
        int c0 = cg * 4 + pass * 256;
        if (c0 >= H3) break;
        float acc[4][4] = {};
        for (int k = 0; k < H3; ++k) {
            float4 w = *reinterpret_cast<const float4*>(&W2[k * H3 + c0]);
            #pragma unroll
            for (int i = 0; i < 4; ++i) {
                float s = sh[r0 + i][k];
                acc[i][0] = fmaf(s, w.x, acc[i][0]);
                acc[i][1] = fmaf(s, w.y, acc[i][1]);
                acc[i][2] = fmaf(s, w.z, acc[i][2]);
                acc[i][3] = fmaf(s, w.w, acc[i][3]);
            }
        }
        #pragma unroll
        for (int i = 0; i < 4; ++i)
            #pragma unroll
            for (int j = 0; j < 4; ++j)
                g_x[(n0 + r0 + i) * H3 + c0 + j] = acc[i][j] + b2[c0 + j];
    }
}

// ---------------- edge filter MLP: phase1 scalar, phase2 FFMA2 row-pairs ----------------
// 64 edges/block, 256 threads. smem: srb + scut + shT[128][66] (~39 KB, static)
#define TSTR 66
__global__ __launch_bounds__(256) void k_edge_filter(
    const float* __restrict__ rbf, const float* __restrict__ cut,
    const float* __restrict__ Wf1, const float* __restrict__ bf1,
    const float* __restrict__ bf2)
{
    __shared__ float srb[64][NR];
    __shared__ float scut[64];
    __shared__ __align__(16) float shT[HH * TSTR];   // hidden, transposed [k][row]
    int tid = threadIdx.x;
    int e0 = blockIdx.x * 64;

    for (int i = tid; i < 64 * NR; i += 256)
        srb[i / NR][i % NR] = rbf[(e0 + i / NR) * NR + (i % NR)];
    if (tid < 64) scut[tid] = cut[e0 + tid];
    __syncthreads();

    // phase 1: hidden[64][128] = silu(rbf@Wf1+bf1), stored transposed
    {
        int rg = tid >> 4;   // 16 row groups of 4
        int cg = tid & 15;   // 16 col groups of 4
        int r0 = rg * 4;
        for (int pass = 0; pass < 2; ++pass) {
            int c0 = cg * 4 + pass * 64;
            float acc[4][4] = {};
            for (int k = 0; k < NR; ++k) {
                float4 w = *reinterpret_cast<const float4*>(&Wf1[k * HH + c0]);
                #pragma unroll
                for (int i = 0; i < 4; ++i) {
                    float s = srb[r0 + i][k];
                    acc[i][0] = fmaf(s, w.x, acc[i][0]);
                    acc[i][1] = fmaf(s, w.y, acc[i][1]);
                    acc[i][2] = fmaf(s, w.z, acc[i][2]);
                    acc[i][3] = fmaf(s, w.w, acc[i][3]);
                }
            }
            #pragma unroll
            for (int i = 0; i < 4; ++i)
                #pragma unroll
                for (int j = 0; j < 4; ++j)
                    shT[(c0 + j) * TSTR + (r0 + i)] = silu_f(acc[i][j] + bf1[c0 + j]);
        }
    }
    __syncthreads();

    // phase 2: filters[64][384] via FFMA2 (row pairs). 8 rows x 4 cols per slot.
    #pragma unroll 1
    for (int pass = 0; pass < 3; ++pass) {
        int slot = pass * 256 + tid;        // 768 slots = 8 row-groups x 96 col-groups
        int rg = slot / 96;                 // warp-uniform (96 | warp boundaries? 32|96 chunks: lanes same rg)
        int cg = slot % 96;
        int r0 = rg * 8;
        int c0 = cg * 4;
        u64 acc[4][4] = {};                 // [row-pair][col]
        #pragma unroll 4
        for (int k = 0; k < HH; ++k) {
            ulonglong2 wa = *(const ulonglong2*)&g_wdup[k * 2 * H3 + 2 * c0];      // cols c0,c0+1 dup
            ulonglong2 wb = *(const ulonglong2*)&g_wdup[k * 2 * H3 + 2 * c0 + 4];  // cols c0+2,c0+3 dup
            u64 a0 = *(const u64*)&shT[k * TSTR + r0];
            u64 a1 = *(const u64*)&shT[k * TSTR + r0 + 2];
            u64 a2 = *(const u64*)&shT[k * TSTR + r0 + 4];
            u64 a3 = *(const u64*)&shT[k * TSTR + r0 + 6];
            acc[0][0] = ffma2(a0, wa.x, acc[0][0]);
            acc[0][1] = ffma2(a0, wa.y, acc[0][1]);
            acc[0][2] = ffma2(a0, wb.x, acc[0][2]);
            acc[0][3] = ffma2(a0, wb.y, acc[0][3]);
            acc[1][0] = ffma2(a1, wa.x, acc[1][0]);
            acc[1][1] = ffma2(a1, wa.y, acc[1][1]);
            acc[1][2] = ffma2(a1, wb.x, acc[1][2]);
            acc[1][3] = ffma2(a1, wb.y, acc[1][3]);
            acc[2][0] = ffma2(a2, wa.x, acc[2][0]);
            acc[2][1] = ffma2(a2, wa.y, acc[2][1]);
            acc[2][2] = ffma2(a2, wb.x, acc[2][2]);
            acc[2][3] = ffma2(a2, wb.y, acc[2][3]);
            acc[3][0] = ffma2(a3, wa.x, acc[3][0]);
            acc[3][1] = ffma2(a3, wa.y, acc[3][1]);
            acc[3][2] = ffma2(a3, wb.x, acc[3][2]);
            acc[3][3] = ffma2(a3, wb.y, acc[3][3]);
        }
        float b0 = bf2[c0], b1v = bf2[c0 + 1], b2v = bf2[c0 + 2], b3 = bf2[c0 + 3];
        #pragma unroll
        for (int p = 0; p < 4; ++p) {
            float lo0, hi0, lo1, hi1, lo2, hi2, lo3, hi3;
            unpack2(acc[p][0], lo0, hi0);
            unpack2(acc[p][1], lo1, hi1);
            unpack2(acc[p][2], lo2, hi2);
            unpack2(acc[p][3], lo3, hi3);
            int rA = r0 + 2 * p, rB = rA + 1;
            float cA = scut[rA], cB = scut[rB];
            *(float4*)&g_filters[(size_t)(e0 + rA) * H3 + c0] =
                make_float4((lo0 + b0) * cA, (lo1 + b1v) * cA, (lo2 + b2v) * cA, (lo3 + b3) * cA);
            *(float4*)&g_filters[(size_t)(e0 + rB) * H3 + c0] =
                make_float4((hi0 + b0) * cB, (hi1 + b1v) * cB, (hi2 + b2v) * cB, (hi3 + b3) * cB);
        }
    }
}

// ---------------- pull aggregation (CSR) -> qmid, mumid ----------------
__global__ __launch_bounds__(128) void k_aggregate(
    const float* __restrict__ q, const float* __restrict__ mu,
    const int* __restrict__ ei, const float* __restrict__ uv)
{
    int n = blockIdx.x;
    int h = threadIdx.x;
    int beg = g_off[n], end = g_off[n + 1];
    float qa = 0.f, m0 = 0.f, m1 = 0.f, m2 = 0.f;
    for (int i = beg; i < end; ++i) {
        int e = g_elist[i];
        int s = ei[NE + e];
        const float* f = &g_filters[(size_t)e * H3];
        float fq = f[h], fr = f[HH + h], fm = f[2 * HH + h];
        const float* xs = &g_x[s * H3];
        float xq = xs[h] * fq;
        float xr = xs[HH + h] * fr;
        float xm = xs[2 * HH + h] * fm;
        float u0 = uv[e * 3 + 0], u1 = uv[e * 3 + 1], u2 = uv[e * 3 + 2];
        const float* ms = &mu[s * 3 * HH];
        qa += xq;
        m0 = fmaf(u0, xr, fmaf(ms[h],          xm, m0));
        m1 = fmaf(u1, xr, fmaf(ms[HH + h],     xm, m1));
        m2 = fmaf(u2, xr, fmaf(ms[2 * HH + h], xm, m2));
    }
    g_qmid[n * HH + h] = q[n * HH + h] + qa;
    g_mumid[n * 3 * HH + h]          = mu[n * 3 * HH + h] + m0;
    g_mumid[n * 3 * HH + HH + h]     = mu[n * 3 * HH + HH + h] + m1;
    g_mumid[n * 3 * HH + 2 * HH + h] = mu[n * 3 * HH + 2 * HH + h] + m2;
}

// ---------------- equivariant linear: vnorm, inner, mu_w ----------------
__global__ __launch_bounds__(256) void k_equiv(const float* __restrict__ Wvec)
{
    __shared__ float smu[24][3 * HH];
    int tid = threadIdx.x;
    int n0 = blockIdx.x * 24;

    for (int i = tid; i < 24 * 3 * HH; i += 256) {
        int r = i / (3 * HH);
        int c = i % (3 * HH);
        int n = n0 + r;
        smu[r][c] = (n < NN) ? g_mumid[n * 3 * HH + c] : 0.f;
    }
    __syncthreads();

    for (int slot = tid; slot < 6 * HH; slot += 256) {
        int ng = slot >> 7;
        int o  = slot & 127;
        int r0 = ng * 4;
        float v[4][3] = {};
        float w[4][3] = {};
        for (int k = 0; k < HH; ++k) {
            float wv = Wvec[k * H2 + o];
            float ww = Wvec[k * H2 + HH + o];
            #pragma unroll
            for (int i = 0; i < 4; ++i)
                #pragma unroll
                for (int d = 0; d < 3; ++d) {
                    float m = smu[r0 + i][d * HH + k];
                    v[i][d] = fmaf(m, wv, v[i][d]);
                    w[i][d] = fmaf(m, ww, w[i][d]);
                }
        }
        #pragma unroll
        for (int i = 0; i < 4; ++i) {
            int n = n0 + r0 + i;
            if (n >= NN) break;
            float vn = sqrtf(v[i][0] * v[i][0] + v[i][1] * v[i][1] +
                             v[i][2] * v[i][2] + 1e-8f);
            float in = v[i][0] * w[i][0] + v[i][1] * w[i][1] + v[i][2] * w[i][2];
            g_vnorm[n * HH + o] = vn;
            g_inner[n * HH + o] = in;
            g_muw[n * 3 * HH + o]          = w[i][0];
            g_muw[n * 3 * HH + HH + o]     = w[i][1];
            g_muw[n * 3 * HH + 2 * HH + o] = w[i][2];
        }
    }
}

// ---------------- scalar mix MLP + final update (Round-1 proven version) ----------------
__global__ __launch_bounds__(256) void k_mix(
    const float* __restrict__ Wm1, const float* __restrict__ bm1,
    const float* __restrict__ Wm2, const float* __restrict__ bm2,
    float* __restrict__ qout, float* __restrict__ muout)
{
    __shared__ float sin_[16][H2];
    __shared__ float shid[16][H3];
    int tid = threadIdx.x;
    int n0 = blockIdx.x * 16;

    for (int i = tid; i < 16 * H2; i += 256) {
        int r = i >> 8;
        int c = i & 255;
        int n = n0 + r;
        float v = 0.f;
        if (n < NN) v = (c < HH) ? g_qmid[n * HH + c] : g_vnorm[n * HH + (c - HH)];
        sin_[r][c] = v;
    }
    __syncthreads();

    int rg = tid >> 6;
    int cg = tid & 63;
    int r0 = rg * 4;

    for (int pass = 0; pass < 2; ++pass) {
        int c0 = cg * 4 + pass * 256;
        if (c0 >= H3) break;
        float acc[4][4] = {};
        for (int k = 0; k < H2; ++k) {
            float4 w = *reinterpret_cast<const float4*>(&Wm1[k * H3 + c0]);
            #pragma unroll
            for (int i = 0; i < 4; ++i) {
                float s = sin_[r0 + i][k];
                acc[i][0] = fmaf(s, w.x, acc[i][0]);
                acc[i][1] = fmaf(s, w.y, acc[i][1]);
                acc[i][2] = fmaf(s, w.z, acc[i][2]);
                acc[i][3] = fmaf(s, w.w, acc[i][3]);
            }
        }
        #pragma unroll
        for (int i = 0; i < 4; ++i)
            #pragma unroll
            for (int j = 0; j < 4; ++j)
                shid[r0 + i][c0 + j] = silu_f(acc[i][j] + bm1[c0 + j]);
    }
    __syncthreads();

    for (int slot = tid; slot < 4 * HH; slot += 256) {
        int ng = slot >> 7;
        int o  = slot & 127;
        int rr0 = ng * 4;
        float aq[4] = {}, as[4] = {}, am[4] = {};
        for (int k = 0; k < H3; ++k) {
            float wq = Wm2[k * H3 + o];
            float ws = Wm2[k * H3 + HH + o];
            float wm = Wm2[k * H3 + 2 * HH + o];
            #pragma unroll
            for (int i = 0; i < 4; ++i) {
                float hv = shid[rr0 + i][k];
                aq[i] = fmaf(hv, wq, aq[i]);
                as[i] = fmaf(hv, ws, as[i]);
                am[i] = fmaf(hv, wm, am[i]);
            }
        }
        #pragma unroll
        for (int i = 0; i < 4; ++i) {
            int n = n0 + rr0 + i;
            if (n >= NN) break;
            float dq  = aq[i] + bm2[o];
            float dms = as[i] + bm2[HH + o];
            float dqm = am[i] + bm2[2 * HH + o];
            qout[n * HH + o] = g_qmid[n * HH + o] + dq + dqm * g_inner[n * HH + o];
            #pragma unroll
            for (int d = 0; d < 3; ++d) {
                int idx = n * 3 * HH + d * HH + o;
                muout[idx] = g_mumid[idx] + g_muw[idx] * dms;
            }
        }
    }
}

// ---------------- launch ----------------
extern "C" void kernel_launch(void* const* d_in, const int* in_sizes, int n_in,
                              void* d_out, int out_size)
{
    const float* q   = (const float*)d_in[0];
    const float* mu  = (const float*)d_in[1];
    const int*   ei  = (const int*)d_in[2];
    const float* rbf = (const float*)d_in[3];
    const float* uv  = (const float*)d_in[4];
    const float* cut = (const float*)d_in[5];
    const float* Wi1 = (const float*)d_in[6];
    const float* bi1 = (const float*)d_in[7];
    const float* Wi2 = (const float*)d_in[8];
    const float* bi2 = (const float*)d_in[9];
    const float* Wf1 = (const float*)d_in[10];
    const float* bf1 = (const float*)d_in[11];
    const float* Wf2 = (const float*)d_in[12];
    const float* bf2 = (const float*)d_in[13];
    const float* Wv  = (const float*)d_in[14];
    const float* Wm1 = (const float*)d_in[15];
    const float* bm1 = (const float*)d_in[16];
    const float* Wm2 = (const float*)d_in[17];
    const float* bm2 = (const float*)d_in[18];

    float* qout  = (float*)d_out;
    float* muout = qout + (size_t)NN * HH;

    // CSR build + weight dup
    k_zero<<<(NN + 255) / 256, 256>>>();
    k_count<<<512, 256>>>(ei);
    k_dupw<<<(HH * H3 + 255) / 256, 256>>>(Wf2);
    k_scan<<<1, 1024>>>();
    k_fill<<<512, 256>>>(ei);

    // dense stages
    k_node_mlp<<<NN / 16, 256>>>(q, Wi1, bi1, Wi2, bi2);
    k_edge_filter<<<NE / 64, 256>>>(rbf, cut, Wf1, bf1, bf2);

    // message aggregation
    k_aggregate<<<NN, 128>>>(q, mu, ei, uv);

    // mixing
    k_equiv<<<(NN + 23) / 24, 256>>>(Wv);
    k_mix<<<(NN + 15) / 16, 256>>>(Wm1, bm1, Wm2, bm2, qout, muout);
}

// round 4
// speedup vs baseline: 1.4187x; 1.2150x over previous
#include <cuda_runtime.h>
#include <math.h>

#define NN 10000
#define NE 256000
#define HH 128
#define H2 256
#define H3 384
#define NR 20

typedef unsigned int u32;

// ---------------- scratch (static device globals; no allocation) ----------------
__device__ float g_x[NN * H3];
__device__ float g_filters[(size_t)NE * H3];
__device__ float g_bhi[HH * H3];               // Wf2 tf32-hi part
__device__ float g_blo[HH * H3];               // Wf2 tf32-lo part
__device__ float g_qmid[NN * HH];
__device__ float g_mumid[NN * 3 * HH];
__device__ float g_vnorm[NN * HH];
__device__ float g_inner[NN * HH];
__device__ float g_muw[NN * 3 * HH];
__device__ int   g_count[NN];
__device__ int   g_off[NN + 1];
__device__ int   g_cursor[NN];
__device__ int   g_elist[NE];

__device__ __forceinline__ float silu_f(float x) {
    return x / (1.0f + __expf(-x));
}

__device__ __forceinline__ u32 cvt_tf32(float x) {
    u32 r;
    asm("cvt.rna.tf32.f32 %0, %1;" : "=r"(r) : "f"(x));
    return r;
}

__device__ __forceinline__ void mma_tf32(float& c0, float& c1, float& c2, float& c3,
                                         u32 a0, u32 a1, u32 a2, u32 a3,
                                         u32 b0, u32 b1) {
    asm("mma.sync.aligned.m16n8k8.row.col.f32.tf32.tf32.f32 "
        "{%0,%1,%2,%3}, {%4,%5,%6,%7}, {%8,%9}, {%0,%1,%2,%3};"
        : "+f"(c0), "+f"(c1), "+f"(c2), "+f"(c3)
        : "r"(a0), "r"(a1), "r"(a2), "r"(a3), "r"(b0), "r"(b1));
}

// ---------------- weight split (one-shot, tiny) ----------------
__global__ void k_splitb(const float* __restrict__ Wf2) {
    int i = blockIdx.x * blockDim.x + threadIdx.x;
    if (i < HH * H3) {
        float w = Wf2[i];
        u32 hb = cvt_tf32(w);
        float hf = __uint_as_float(hb);
        u32 lb = cvt_tf32(w - hf);
        g_bhi[i] = __uint_as_float(hb);
        g_blo[i] = __uint_as_float(lb);
    }
}

// ---------------- CSR build ----------------
__global__ void k_zero() {
    int i = blockIdx.x * blockDim.x + threadIdx.x;
    if (i < NN) g_count[i] = 0;
}

__global__ void k_count(const int* __restrict__ ei) {
    for (int e = blockIdx.x * blockDim.x + threadIdx.x; e < NE;
         e += gridDim.x * blockDim.x)
        atomicAdd(&g_count[ei[e]], 1);
}

__global__ __launch_bounds__(1024) void k_scan() {
    __shared__ int ps[1024];
    int tid = threadIdx.x;
    const int CH = (NN + 1023) / 1024;
    int base = tid * CH;
    int s = 0;
    for (int j = 0; j < CH; ++j) {
        int idx = base + j;
        if (idx < NN) s += g_count[idx];
    }
    ps[tid] = s;
    __syncthreads();
    for (int off = 1; off < 1024; off <<= 1) {
        int v = 0;
        if (tid >= off) v = ps[tid - off];
        __syncthreads();
        ps[tid] += v;
        __syncthreads();
    }
    int run = ps[tid] - s;
    for (int j = 0; j < CH; ++j) {
        int idx = base + j;
        if (idx < NN) {
            g_off[idx] = run;
            g_cursor[idx] = run;
            run += g_count[idx];
        }
    }
    if (tid == 1023) g_off[NN] = ps[1023];
}

__global__ void k_fill(const int* __restrict__ ei) {
    for (int e = blockIdx.x * blockDim.x + threadIdx.x; e < NE;
         e += gridDim.x * blockDim.x) {
        int t = ei[e];
        int pos = atomicAdd(&g_cursor[t], 1);
        g_elist[pos] = e;
    }
}

// ---------------- node inter MLP (Round-1 proven) ----------------
__global__ __launch_bounds__(256) void k_node_mlp(
    const float* __restrict__ q,
    const float* __restrict__ W1, const float* __restrict__ b1,
    const float* __restrict__ W2, const float* __restrict__ b2)
{
    __shared__ float sq[16][HH];
    __shared__ float sh[16][H3];
    int tid = threadIdx.x;
    int n0 = blockIdx.x * 16;

    for (int i = tid; i < 16 * HH; i += 256)
        sq[i / HH][i % HH] = q[(n0 + i / HH) * HH + (i % HH)];
    __syncthreads();

    int rg = tid >> 6;
    int cg = tid & 63;
    int r0 = rg * 4;

    for (int pass = 0; pass < 2; ++pass) {
        int c0 = cg * 4 + pass * 256;
        if (c0 >= H3) break;
        float acc[4][4] = {};
        for (int k = 0; k < HH; ++k) {
            float4 w = *reinterpret_cast<const float4*>(&W1[k * H3 + c0]);
            #pragma unroll
            for (int i = 0; i < 4; ++i) {
                float s = sq[r0 + i][k];
                acc[i][0] = fmaf(s, w.x, acc[i][0]);
                acc[i][1] = fmaf(s, w.y, acc[i][1]);
                acc[i][2] = fmaf(s, w.z, acc[i][2]);
                acc[i][3] = fmaf(s, w.w, acc[i][3]);
            }
        }
        #pragma unroll
        for (int i = 0; i < 4; ++i)
            #pragma unroll
            for (int j = 0; j < 4; ++j)
                sh[r0 + i][c0 + j] = silu_f(acc[i][j] + b1[c0 + j]);
    }
    __syncthreads();

    for (int pass = 0; pass < 2; ++pass) {
        int c0 = cg * 4 + pass * 256;
        if (c0 >= H3) break;
        float acc[4][4] = {};
        for (int k = 0; k < H3; ++k) {
            float4 w = *reinterpret_cast<const float4*>(&W2[k * H3 + c0]);
            #pragma unroll
            for (int i = 0; i < 4; ++i) {
                float s = sh[r0 + i][k];
                acc[i][0] = fmaf(s, w.x, acc[i][0]);
                acc[i][1] = fmaf(s, w.y, acc[i][1]);
                acc[i][2] = fmaf(s, w.z, acc[i][2]);
                acc[i][3] = fmaf(s, w.w, acc[i][3]);
            }
        }
        #pragma unroll
        for (int i = 0; i < 4; ++i)
            #pragma unroll
            for (int j = 0; j < 4; ++j)
                g_x[(n0 + r0 + i) * H3 + c0 + j] = acc[i][j] + b2[c0 + j];
    }
}

// ---------------- edge filter MLP: phase1 scalar, phase2 tf32 mma (3-split) ----------------
// 64 edges/block, 256 threads (8 warps). Each warp: 4 row-tiles x 6 n-tiles.
#define SHP 132
__global__ __launch_bounds__(256) void k_edge_filter(
    const float* __restrict__ rbf, const float* __restrict__ cut,
    const float* __restrict__ Wf1, const float* __restrict__ bf1,
    const float* __restrict__ bf2)
{
    __shared__ float srb[64][NR];
    __shared__ float scut[64];
    __shared__ __align__(16) float sh[64 * SHP];   // hidden [row][k], stride 132
    int tid = threadIdx.x;
    int e0 = blockIdx.x * 64;

    for (int i = tid; i < 64 * NR; i += 256)
        srb[i / NR][i % NR] = rbf[(e0 + i / NR) * NR + (i % NR)];
    if (tid < 64) scut[tid] = cut[e0 + tid];
    __syncthreads();

    // phase 1: hidden[64][128] = silu(rbf@Wf1+bf1)  (scalar, cheap: K=20)
    {
        int rg = tid >> 4;
        int cg = tid & 15;
        int r0 = rg * 4;
        for (int pass = 0; pass < 2; ++pass) {
            int c0 = cg * 4 + pass * 64;
            float acc[4][4] = {};
            for (int k = 0; k < NR; ++k) {
                float4 w = *reinterpret_cast<const float4*>(&Wf1[k * HH + c0]);
                #pragma unroll
                for (int i = 0; i < 4; ++i) {
                    float s = srb[r0 + i][k];
                    acc[i][0] = fmaf(s, w.x, acc[i][0]);
                    acc[i][1] = fmaf(s, w.y, acc[i][1]);
                    acc[i][2] = fmaf(s, w.z, acc[i][2]);
                    acc[i][3] = fmaf(s, w.w, acc[i][3]);
                }
            }
            #pragma unroll
            for (int i = 0; i < 4; ++i)
                #pragma unroll
                for (int j = 0; j < 4; ++j)
                    sh[(r0 + i) * SHP + c0 + j] = silu_f(acc[i][j] + bf1[c0 + j]);
        }
    }
    __syncthreads();

    // phase 2: filters[64][384] = hidden @ Wf2 via m16n8k8 tf32 mma, 3-term split
    int wid  = tid >> 5;
    int lane = tid & 31;
    int gid  = lane >> 2;     // 0..7
    int tig  = lane & 3;      // 0..3
    int nbase = wid * 48;     // 6 n-tiles of 8 per warp

    float acc[4][6][4];
    #pragma unroll
    for (int r = 0; r < 4; ++r)
        #pragma unroll
        for (int t = 0; t < 6; ++t)
            #pragma unroll
            for (int c = 0; c < 4; ++c)
                acc[r][t][c] = 0.f;

    #pragma unroll 1
    for (int k0 = 0; k0 < HH; k0 += 8) {
        // B fragments (hi and lo) for 6 n-tiles
        u32 bh[6][2], bl[6][2];
        #pragma unroll
        for (int t = 0; t < 6; ++t) {
            int col = nbase + t * 8 + gid;
            int ro0 = (k0 + tig) * H3 + col;
            int ro1 = (k0 + tig + 4) * H3 + col;
            bh[t][0] = __float_as_uint(__ldg(&g_bhi[ro0]));
            bh[t][1] = __float_as_uint(__ldg(&g_bhi[ro1]));
            bl[t][0] = __float_as_uint(__ldg(&g_blo[ro0]));
            bl[t][1] = __float_as_uint(__ldg(&g_blo[ro1]));
        }
        #pragma unroll
        for (int r = 0; r < 4; ++r) {
            int rb = r * 16;
            float a0f = sh[(rb + gid) * SHP + k0 + tig];
            float a1f = sh[(rb + gid + 8) * SHP + k0 + tig];
            float a2f = sh[(rb + gid) * SHP + k0 + tig + 4];
            float a3f = sh[(rb + gid + 8) * SHP + k0 + tig + 4];
            u32 ah0 = cvt_tf32(a0f), ah1 = cvt_tf32(a1f);
            u32 ah2 = cvt_tf32(a2f), ah3 = cvt_tf32(a3f);
            u32 al0 = cvt_tf32(a0f - __uint_as_float(ah0));
            u32 al1 = cvt_tf32(a1f - __uint_as_float(ah1));
            u32 al2 = cvt_tf32(a2f - __uint_as_float(ah2));
            u32 al3 = cvt_tf32(a3f - __uint_as_float(ah3));
            #pragma unroll
            for (int t = 0; t < 6; ++t) {
                mma_tf32(acc[r][t][0], acc[r][t][1], acc[r][t][2], acc[r][t][3],
                         ah0, ah1, ah2, ah3, bh[t][0], bh[t][1]);
                mma_tf32(acc[r][t][0], acc[r][t][1], acc[r][t][2], acc[r][t][3],
                         al0, al1, al2, al3, bh[t][0], bh[t][1]);
                mma_tf32(acc[r][t][0], acc[r][t][1], acc[r][t][2], acc[r][t][3],
                         ah0, ah1, ah2, ah3, bl[t][0], bl[t][1]);
            }
        }
    }

    // epilogue: bias + cutoff, store
    #pragma unroll
    for (int r = 0; r < 4; ++r) {
        int row0 = r * 16 + gid;
        int row1 = row0 + 8;
        float c0v = scut[row0];
        float c1v = scut[row1];
        #pragma unroll
        for (int t = 0; t < 6; ++t) {
            int col = nbase + t * 8 + 2 * tig;
            float b0v = bf2[col];
            float b1v = bf2[col + 1];
            float2 v0 = make_float2((acc[r][t][0] + b0v) * c0v,
                                    (acc[r][t][1] + b1v) * c0v);
            float2 v1 = make_float2((acc[r][t][2] + b0v) * c1v,
                                    (acc[r][t][3] + b1v) * c1v);
            *(float2*)&g_filters[(size_t)(e0 + row0) * H3 + col] = v0;
            *(float2*)&g_filters[(size_t)(e0 + row1) * H3 + col] = v1;
        }
    }
}

// ---------------- pull aggregation (CSR) -> qmid, mumid ----------------
__global__ __launch_bounds__(128) void k_aggregate(
    const float* __restrict__ q, const float* __restrict__ mu,
    const int* __restrict__ ei, const float* __restrict__ uv)
{
    int n = blockIdx.x;
    int h = threadIdx.x;
    int beg = g_off[n], end = g_off[n + 1];
    float qa = 0.f, m0 = 0.f, m1 = 0.f, m2 = 0.f;
    for (int i = beg; i < end; ++i) {
        int e = g_elist[i];
        int s = ei[NE + e];
        const float* f = &g_filters[(size_t)e * H3];
        float fq = f[h], fr = f[HH + h], fm = f[2 * HH + h];
        const float* xs = &g_x[s * H3];
        float xq = xs[h] * fq;
        float xr = xs[HH + h] * fr;
        float xm = xs[2 * HH + h] * fm;
        float u0 = uv[e * 3 + 0], u1 = uv[e * 3 + 1], u2 = uv[e * 3 + 2];
        const float* ms = &mu[s * 3 * HH];
        qa += xq;
        m0 = fmaf(u0, xr, fmaf(ms[h],          xm, m0));
        m1 = fmaf(u1, xr, fmaf(ms[HH + h],     xm, m1));
        m2 = fmaf(u2, xr, fmaf(ms[2 * HH + h], xm, m2));
    }
    g_qmid[n * HH + h] = q[n * HH + h] + qa;
    g_mumid[n * 3 * HH + h]          = mu[n * 3 * HH + h] + m0;
    g_mumid[n * 3 * HH + HH + h]     = mu[n * 3 * HH + HH + h] + m1;
    g_mumid[n * 3 * HH + 2 * HH + h] = mu[n * 3 * HH + 2 * HH + h] + m2;
}

// ---------------- equivariant linear: vnorm, inner, mu_w ----------------
__global__ __launch_bounds__(256) void k_equiv(const float* __restrict__ Wvec)
{
    __shared__ float smu[24][3 * HH];
    int tid = threadIdx.x;
    int n0 = blockIdx.x * 24;

    for (int i = tid; i < 24 * 3 * HH; i += 256) {
        int r = i / (3 * HH);
        int c = i % (3 * HH);
        int n = n0 + r;
        smu[r][c] = (n < NN) ? g_mumid[n * 3 * HH + c] : 0.f;
    }
    __syncthreads();

    for (int slot = tid; slot < 6 * HH; slot += 256) {
        int ng = slot >> 7;
        int o  = slot & 127;
        int r0 = ng * 4;
        float v[4][3] = {};
        float w[4][3] = {};
        for (int k = 0; k < HH; ++k) {
            float wv = Wvec[k * H2 + o];
            float ww = Wvec[k * H2 + HH + o];
            #pragma unroll
            for (int i = 0; i < 4; ++i)
                #pragma unroll
                for (int d = 0; d < 3; ++d) {
                    float m = smu[r0 + i][d * HH + k];
                    v[i][d] = fmaf(m, wv, v[i][d]);
                    w[i][d] = fmaf(m, ww, w[i][d]);
                }
        }
        #pragma unroll
        for (int i = 0; i < 4; ++i) {
            int n = n0 + r0 + i;
            if (n >= NN) break;
            float vn = sqrtf(v[i][0] * v[i][0] + v[i][1] * v[i][1] +
                             v[i][2] * v[i][2] + 1e-8f);
            float in = v[i][0] * w[i][0] + v[i][1] * w[i][1] + v[i][2] * w[i][2];
            g_vnorm[n * HH + o] = vn;
            g_inner[n * HH + o] = in;
            g_muw[n * 3 * HH + o]          = w[i][0];
            g_muw[n * 3 * HH + HH + o]     = w[i][1];
            g_muw[n * 3 * HH + 2 * HH + o] = w[i][2];
        }
    }
}

// ---------------- scalar mix MLP + final update (Round-1 proven) ----------------
__global__ __launch_bounds__(256) void k_mix(
    const float* __restrict__ Wm1, const float* __restrict__ bm1,
    const float* __restrict__ Wm2, const float* __restrict__ bm2,
    float* __restrict__ qout, float* __restrict__ muout)
{
    __shared__ float sin_[16][H2];
    __shared__ float shid[16][H3];
    int tid = threadIdx.x;
    int n0 = blockIdx.x * 16;

    for (int i = tid; i < 16 * H2; i += 256) {
        int r = i >> 8;
        int c = i & 255;
        int n = n0 + r;
        float v = 0.f;
        if (n < NN) v = (c < HH) ? g_qmid[n * HH + c] : g_vnorm[n * HH + (c - HH)];
        sin_[r][c] = v;
    }
    __syncthreads();

    int rg = tid >> 6;
    int cg = tid & 63;
    int r0 = rg * 4;

    for (int pass = 0; pass < 2; ++pass) {
        int c0 = cg * 4 + pass * 256;
        if (c0 >= H3) break;
        float acc[4][4] = {};
        for (int k = 0; k < H2; ++k) {
            float4 w = *reinterpret_cast<const float4*>(&Wm1[k * H3 + c0]);
            #pragma unroll
            for (int i = 0; i < 4; ++i) {
                float s = sin_[r0 + i][k];
                acc[i][0] = fmaf(s, w.x, acc[i][0]);
                acc[i][1] = fmaf(s, w.y, acc[i][1]);
                acc[i][2] = fmaf(s, w.z, acc[i][2]);
                acc[i][3] = fmaf(s, w.w, acc[i][3]);
            }
        }
        #pragma unroll
        for (int i = 0; i < 4; ++i)
            #pragma unroll
            for (int j = 0; j < 4; ++j)
                shid[r0 + i][c0 + j] = silu_f(acc[i][j] + bm1[c0 + j]);
    }
    __syncthreads();

    for (int slot = tid; slot < 4 * HH; slot += 256) {
        int ng = slot >> 7;
        int o  = slot & 127;
        int rr0 = ng * 4;
        float aq[4] = {}, as[4] = {}, am[4] = {};
        for (int k = 0; k < H3; ++k) {
            float wq = Wm2[k * H3 + o];
            float ws = Wm2[k * H3 + HH + o];
            float wm = Wm2[k * H3 + 2 * HH + o];
            #pragma unroll
            for (int i = 0; i < 4; ++i) {
                float hv = shid[rr0 + i][k];
                aq[i] = fmaf(hv, wq, aq[i]);
                as[i] = fmaf(hv, ws, as[i]);
                am[i] = fmaf(hv, wm, am[i]);
            }
        }
        #pragma unroll
        for (int i = 0; i < 4; ++i) {
            int n = n0 + rr0 + i;
            if (n >= NN) break;
            float dq  = aq[i] + bm2[o];
            float dms = as[i] + bm2[HH + o];
            float dqm = am[i] + bm2[2 * HH + o];
            qout[n * HH + o] = g_qmid[n * HH + o] + dq + dqm * g_inner[n * HH + o];
            #pragma unroll
            for (int d = 0; d < 3; ++d) {
                int idx = n * 3 * HH + d * HH + o;
                muout[idx] = g_mumid[idx] + g_muw[idx] * dms;
            }
        }
    }
}

// ---------------- launch ----------------
extern "C" void kernel_launch(void* const* d_in, const int* in_sizes, int n_in,
                              void* d_out, int out_size)
{
    const float* q   = (const float*)d_in[0];
    const float* mu  = (const float*)d_in[1];
    const int*   ei  = (const int*)d_in[2];
    const float* rbf = (const float*)d_in[3];
    const float* uv  = (const float*)d_in[4];
    const float* cut = (const float*)d_in[5];
    const float* Wi1 = (const float*)d_in[6];
    const float* bi1 = (const float*)d_in[7];
    const float* Wi2 = (const float*)d_in[8];
    const float* bi2 = (const float*)d_in[9];
    const float* Wf1 = (const float*)d_in[10];
    const float* bf1 = (const float*)d_in[11];
    const float* Wf2 = (const float*)d_in[12];
    const float* bf2 = (const float*)d_in[13];
    const float* Wv  = (const float*)d_in[14];
    const float* Wm1 = (const float*)d_in[15];
    const float* bm1 = (const float*)d_in[16];
    const float* Wm2 = (const float*)d_in[17];
    const float* bm2 = (const float*)d_in[18];

    float* qout  = (float*)d_out;
    float* muout = qout + (size_t)NN * HH;

    // CSR build + weight split
    k_zero<<<(NN + 255) / 256, 256>>>();
    k_count<<<512, 256>>>(ei);
    k_splitb<<<(HH * H3 + 255) / 256, 256>>>(Wf2);
    k_scan<<<1, 1024>>>();
    k_fill<<<512, 256>>>(ei);

    // dense stages
    k_node_mlp<<<NN / 16, 256>>>(q, Wi1, bi1, Wi2, bi2);
    k_edge_filter<<<NE / 64, 256>>>(rbf, cut, Wf1, bf1, bf2);

    // message aggregation
    k_aggregate<<<NN, 128>>>(q, mu, ei, uv);

    // mixing
    k_equiv<<<(NN + 23) / 24, 256>>>(Wv);
    k_mix<<<(NN + 15) / 16, 256>>>(Wm1, bm1, Wm2, bm2, qout, muout);
}

// round 5
// speedup vs baseline: 1.6316x; 1.1500x over previous
#include <cuda_runtime.h>
#include <cuda_bf16.h>
#include <math.h>

#define NN 10000
#define NE 256000
#define HH 128
#define H2 256
#define H3 384
#define NR 20

typedef unsigned int u32;

// ---------------- scratch (static device globals; no allocation) ----------------
__device__ float g_x[NN * H3];
__device__ float g_filters[(size_t)NE * H3];
__device__ u32   g_bhp[(HH / 2) * H3];         // Wf2 bf16-hi, k-pairs packed
__device__ u32   g_blp[(HH / 2) * H3];         // Wf2 bf16-lo residual, k-pairs packed
__device__ float g_qmid[NN * HH];
__device__ float g_mumid[NN * 3 * HH];
__device__ float g_vnorm[NN * HH];
__device__ float g_inner[NN * HH];
__device__ float g_muw[NN * 3 * HH];
__device__ int   g_count[NN];
__device__ int   g_off[NN + 1];
__device__ int   g_cursor[NN];
__device__ int   g_elist[NE];

__device__ __forceinline__ float silu_f(float x) {
    return x / (1.0f + __expf(-x));
}

// pack two f32 -> bf16x2 (lo = first arg, hi = second arg)
__device__ __forceinline__ u32 pack_bf16x2(float lo, float hi) {
    u32 r;
    asm("cvt.rn.bf16x2.f32 %0, %1, %2;" : "=r"(r) : "f"(hi), "f"(lo));
    return r;
}

__device__ __forceinline__ void mma_bf16(float& c0, float& c1, float& c2, float& c3,
                                         u32 a0, u32 a1, u32 a2, u32 a3,
                                         u32 b0, u32 b1) {
    asm("mma.sync.aligned.m16n8k16.row.col.f32.bf16.bf16.f32 "
        "{%0,%1,%2,%3}, {%4,%5,%6,%7}, {%8,%9}, {%0,%1,%2,%3};"
        : "+f"(c0), "+f"(c1), "+f"(c2), "+f"(c3)
        : "r"(a0), "r"(a1), "r"(a2), "r"(a3), "r"(b0), "r"(b1));
}

// ---------------- weight split (one-shot, tiny) ----------------
__global__ void k_splitb(const float* __restrict__ Wf2) {
    int i = blockIdx.x * blockDim.x + threadIdx.x;   // over (HH/2)*H3
    if (i < (HH / 2) * H3) {
        int p = i / H3, col = i % H3;
        float w0 = Wf2[(2 * p) * H3 + col];
        float w1 = Wf2[(2 * p + 1) * H3 + col];
        u32 h01 = pack_bf16x2(w0, w1);
        float h0 = __uint_as_float(h01 << 16);
        float h1 = __uint_as_float(h01 & 0xFFFF0000u);
        u32 l01 = pack_bf16x2(w0 - h0, w1 - h1);
        g_bhp[i] = h01;
        g_blp[i] = l01;
    }
}

// ---------------- CSR build ----------------
__global__ void k_zero() {
    int i = blockIdx.x * blockDim.x + threadIdx.x;
    if (i < NN) g_count[i] = 0;
}

__global__ void k_count(const int* __restrict__ ei) {
    for (int e = blockIdx.x * blockDim.x + threadIdx.x; e < NE;
         e += gridDim.x * blockDim.x)
        atomicAdd(&g_count[ei[e]], 1);
}

__global__ __launch_bounds__(1024) void k_scan() {
    __shared__ int ps[1024];
    int tid = threadIdx.x;
    const int CH = (NN + 1023) / 1024;
    int base = tid * CH;
    int s = 0;
    for (int j = 0; j < CH; ++j) {
        int idx = base + j;
        if (idx < NN) s += g_count[idx];
    }
    ps[tid] = s;
    __syncthreads();
    for (int off = 1; off < 1024; off <<= 1) {
        int v = 0;
        if (tid >= off) v = ps[tid - off];
        __syncthreads();
        ps[tid] += v;
        __syncthreads();
    }
    int run = ps[tid] - s;
    for (int j = 0; j < CH; ++j) {
        int idx = base + j;
        if (idx < NN) {
            g_off[idx] = run;
            g_cursor[idx] = run;
            run += g_count[idx];
        }
    }
    if (tid == 1023) g_off[NN] = ps[1023];
}

__global__ void k_fill(const int* __restrict__ ei) {
    for (int e = blockIdx.x * blockDim.x + threadIdx.x; e < NE;
         e += gridDim.x * blockDim.x) {
        int t = ei[e];
        int pos = atomicAdd(&g_cursor[t], 1);
        g_elist[pos] = e;
    }
}

// ---------------- node inter MLP (Round-1 proven) ----------------
__global__ __launch_bounds__(256) void k_node_mlp(
    const float* __restrict__ q,
    const float* __restrict__ W1, const float* __restrict__ b1,
    const float* __restrict__ W2, const float* __restrict__ b2)
{
    __shared__ float sq[16][HH];
    __shared__ float sh[16][H3];
    int tid = threadIdx.x;
    int n0 = blockIdx.x * 16;

    for (int i = tid; i < 16 * HH; i += 256)
        sq[i / HH][i % HH] = q[(n0 + i / HH) * HH + (i % HH)];
    __syncthreads();

    int rg = tid >> 6;
    int cg = tid & 63;
    int r0 = rg * 4;

    for (int pass = 0; pass < 2; ++pass) {
        int c0 = cg * 4 + pass * 256;
        if (c0 >= H3) break;
        float acc[4][4] = {};
        for (int k = 0; k < HH; ++k) {
            float4 w = *reinterpret_cast<const float4*>(&W1[k * H3 + c0]);
            #pragma unroll
            for (int i = 0; i < 4; ++i) {
                float s = sq[r0 + i][k];
                acc[i][0] = fmaf(s, w.x, acc[i][0]);
                acc[i][1] = fmaf(s, w.y, acc[i][1]);
                acc[i][2] = fmaf(s, w.z, acc[i][2]);
                acc[i][3] = fmaf(s, w.w, acc[i][3]);
            }
        }
        #pragma unroll
        for (int i = 0; i < 4; ++i)
            #pragma unroll
            for (int j = 0; j < 4; ++j)
                sh[r0 + i][c0 + j] = silu_f(acc[i][j] + b1[c0 + j]);
    }
    __syncthreads();

    for (int pass = 0; pass < 2; ++pass) {
        int c0 = cg * 4 + pass * 256;
        if (c0 >= H3) break;
        float acc[4][4] = {};
        for (int k = 0; k < H3; ++k) {
            float4 w = *reinterpret_cast<const float4*>(&W2[k * H3 + c0]);
            #pragma unroll
            for (int i = 0; i < 4; ++i) {
                float s = sh[r0 + i][k];
                acc[i][0] = fmaf(s, w.x, acc[i][0]);
                acc[i][1] = fmaf(s, w.y, acc[i][1]);
                acc[i][2] = fmaf(s, w.z, acc[i][2]);
                acc[i][3] = fmaf(s, w.w, acc[i][3]);
            }
        }
        #pragma unroll
        for (int i = 0; i < 4; ++i)
            #pragma unroll
            for (int j = 0; j < 4; ++j)
                g_x[(n0 + r0 + i) * H3 + c0 + j] = acc[i][j] + b2[c0 + j];
    }
}

// ---------------- edge filter MLP: phase1 scalar, phase2 bf16 mma (3-split) ----------------
// 64 edges/block, 256 threads (8 warps). Each warp: 4 row-tiles x 6 n-tiles.
#define SHP 132
__global__ __launch_bounds__(256) void k_edge_filter(
    const float* __restrict__ rbf, const float* __restrict__ cut,
    const float* __restrict__ Wf1, const float* __restrict__ bf1,
    const float* __restrict__ bf2)
{
    __shared__ float srb[64][NR];
    __shared__ float scut[64];
    __shared__ __align__(16) float sh[64 * SHP];   // hidden [row][k], stride 132
    int tid = threadIdx.x;
    int e0 = blockIdx.x * 64;

    for (int i = tid; i < 64 * NR; i += 256)
        srb[i / NR][i % NR] = rbf[(e0 + i / NR) * NR + (i % NR)];
    if (tid < 64) scut[tid] = cut[e0 + tid];
    __syncthreads();

    // phase 1: hidden[64][128] = silu(rbf@Wf1+bf1)  (scalar, cheap: K=20)
    {
        int rg = tid >> 4;
        int cg = tid & 15;
        int r0 = rg * 4;
        for (int pass = 0; pass < 2; ++pass) {
            int c0 = cg * 4 + pass * 64;
            float acc[4][4] = {};
            for (int k = 0; k < NR; ++k) {
                float4 w = *reinterpret_cast<const float4*>(&Wf1[k * HH + c0]);
                #pragma unroll
                for (int i = 0; i < 4; ++i) {
                    float s = srb[r0 + i][k];
                    acc[i][0] = fmaf(s, w.x, acc[i][0]);
                    acc[i][1] = fmaf(s, w.y, acc[i][1]);
                    acc[i][2] = fmaf(s, w.z, acc[i][2]);
                    acc[i][3] = fmaf(s, w.w, acc[i][3]);
                }
            }
            #pragma unroll
            for (int i = 0; i < 4; ++i)
                #pragma unroll
                for (int j = 0; j < 4; ++j)
                    sh[(r0 + i) * SHP + c0 + j] = silu_f(acc[i][j] + bf1[c0 + j]);
        }
    }
    __syncthreads();

    // phase 2: filters[64][384] = hidden @ Wf2 via m16n8k16 bf16 mma, 3-term split
    int wid  = tid >> 5;
    int lane = tid & 31;
    int gid  = lane >> 2;     // 0..7
    int tig  = lane & 3;      // 0..3
    int nbase = wid * 48;     // 6 n-tiles of 8 per warp

    float acc[4][6][4];
    #pragma unroll
    for (int r = 0; r < 4; ++r)
        #pragma unroll
        for (int t = 0; t < 6; ++t)
            #pragma unroll
            for (int c = 0; c < 4; ++c)
                acc[r][t][c] = 0.f;

    #pragma unroll 1
    for (int k0 = 0; k0 < HH; k0 += 16) {
        int kp = k0 >> 1;     // k-pair base index
        // B fragments (hi and lo) for 6 n-tiles
        u32 bh[6][2], bl[6][2];
        #pragma unroll
        for (int t = 0; t < 6; ++t) {
            int col = nbase + t * 8 + gid;
            int i0 = (kp + tig) * H3 + col;
            int i1 = (kp + 4 + tig) * H3 + col;
            bh[t][0] = __ldg(&g_bhp[i0]);
            bh[t][1] = __ldg(&g_bhp[i1]);
            bl[t][0] = __ldg(&g_blp[i0]);
            bl[t][1] = __ldg(&g_blp[i1]);
        }
        #pragma unroll
        for (int r = 0; r < 4; ++r) {
            int rb = r * 16;
            // A: rows rb+gid, rb+gid+8; cols k0+2tig..+1 and k0+8+2tig..+1
            float2 f0 = *(const float2*)&sh[(rb + gid)     * SHP + k0 + 2 * tig];
            float2 f1 = *(const float2*)&sh[(rb + gid + 8) * SHP + k0 + 2 * tig];
            float2 f2 = *(const float2*)&sh[(rb + gid)     * SHP + k0 + 8 + 2 * tig];
            float2 f3 = *(const float2*)&sh[(rb + gid + 8) * SHP + k0 + 8 + 2 * tig];
            u32 ah0 = pack_bf16x2(f0.x, f0.y);
            u32 ah1 = pack_bf16x2(f1.x, f1.y);
            u32 ah2 = pack_bf16x2(f2.x, f2.y);
            u32 ah3 = pack_bf16x2(f3.x, f3.y);
            u32 al0 = pack_bf16x2(f0.x - __uint_as_float(ah0 << 16),
                                  f0.y - __uint_as_float(ah0 & 0xFFFF0000u));
            u32 al1 = pack_bf16x2(f1.x - __uint_as_float(ah1 << 16),
                                  f1.y - __uint_as_float(ah1 & 0xFFFF0000u));
            u32 al2 = pack_bf16x2(f2.x - __uint_as_float(ah2 << 16),
                                  f2.y - __uint_as_float(ah2 & 0xFFFF0000u));
            u32 al3 = pack_bf16x2(f3.x - __uint_as_float(ah3 << 16),
                                  f3.y - __uint_as_float(ah3 & 0xFFFF0000u));
            #pragma unroll
            for (int t = 0; t < 6; ++t) {
                mma_bf16(acc[r][t][0], acc[r][t][1], acc[r][t][2], acc[r][t][3],
                         ah0, ah1, ah2, ah3, bh[t][0], bh[t][1]);
                mma_bf16(acc[r][t][0], acc[r][t][1], acc[r][t][2], acc[r][t][3],
                         al0, al1, al2, al3, bh[t][0], bh[t][1]);
                mma_bf16(acc[r][t][0], acc[r][t][1], acc[r][t][2], acc[r][t][3],
                         ah0, ah1, ah2, ah3, bl[t][0], bl[t][1]);
            }
        }
    }

    // epilogue: bias + cutoff, store
    #pragma unroll
    for (int r = 0; r < 4; ++r) {
        int row0 = r * 16 + gid;
        int row1 = row0 + 8;
        float c0v = scut[row0];
        float c1v = scut[row1];
        #pragma unroll
        for (int t = 0; t < 6; ++t) {
            int col = nbase + t * 8 + 2 * tig;
            float b0v = bf2[col];
            float b1v = bf2[col + 1];
            float2 v0 = make_float2((acc[r][t][0] + b0v) * c0v,
                                    (acc[r][t][1] + b1v) * c0v);
            float2 v1 = make_float2((acc[r][t][2] + b0v) * c1v,
                                    (acc[r][t][3] + b1v) * c1v);
            *(float2*)&g_filters[(size_t)(e0 + row0) * H3 + col] = v0;
            *(float2*)&g_filters[(size_t)(e0 + row1) * H3 + col] = v1;
        }
    }
}

// ---------------- pull aggregation (CSR) -> qmid, mumid ----------------
__global__ __launch_bounds__(128) void k_aggregate(
    const float* __restrict__ q, const float* __restrict__ mu,
    const int* __restrict__ ei, const float* __restrict__ uv)
{
    int n = blockIdx.x;
    int h = threadIdx.x;
    int beg = g_off[n], end = g_off[n + 1];
    float qa = 0.f, m0 = 0.f, m1 = 0.f, m2 = 0.f;
    for (int i = beg; i < end; ++i) {
        int e = g_elist[i];
        int s = ei[NE + e];
        const float* f = &g_filters[(size_t)e * H3];
        float fq = f[h], fr = f[HH + h], fm = f[2 * HH + h];
        const float* xs = &g_x[s * H3];
        float xq = xs[h] * fq;
        float xr = xs[HH + h] * fr;
        float xm = xs[2 * HH + h] * fm;
        float u0 = uv[e * 3 + 0], u1 = uv[e * 3 + 1], u2 = uv[e * 3 + 2];
        const float* ms = &mu[s * 3 * HH];
        qa += xq;
        m0 = fmaf(u0, xr, fmaf(ms[h],          xm, m0));
        m1 = fmaf(u1, xr, fmaf(ms[HH + h],     xm, m1));
        m2 = fmaf(u2, xr, fmaf(ms[2 * HH + h], xm, m2));
    }
    g_qmid[n * HH + h] = q[n * HH + h] + qa;
    g_mumid[n * 3 * HH + h]          = mu[n * 3 * HH + h] + m0;
    g_mumid[n * 3 * HH + HH + h]     = mu[n * 3 * HH + HH + h] + m1;
    g_mumid[n * 3 * HH + 2 * HH + h] = mu[n * 3 * HH + 2 * HH + h] + m2;
}

// ---------------- equivariant linear: vnorm, inner, mu_w ----------------
__global__ __launch_bounds__(256) void k_equiv(const float* __restrict__ Wvec)
{
    __shared__ float smu[24][3 * HH];
    int tid = threadIdx.x;
    int n0 = blockIdx.x * 24;

    for (int i = tid; i < 24 * 3 * HH; i += 256) {
        int r = i / (3 * HH);
        int c = i % (3 * HH);
        int n = n0 + r;
        smu[r][c] = (n < NN) ? g_mumid[n * 3 * HH + c] : 0.f;
    }
    __syncthreads();

    for (int slot = tid; slot < 6 * HH; slot += 256) {
        int ng = slot >> 7;
        int o  = slot & 127;
        int r0 = ng * 4;
        float v[4][3] = {};
        float w[4][3] = {};
        for (int k = 0; k < HH; ++k) {
            float wv = Wvec[k * H2 + o];
            float ww = Wvec[k * H2 + HH + o];
            #pragma unroll
            for (int i = 0; i < 4; ++i)
                #pragma unroll
                for (int d = 0; d < 3; ++d) {
                    float m = smu[r0 + i][d * HH + k];
                    v[i][d] = fmaf(m, wv, v[i][d]);
                    w[i][d] = fmaf(m, ww, w[i][d]);
                }
        }
        #pragma unroll
        for (int i = 0; i < 4; ++i) {
            int n = n0 + r0 + i;
            if (n >= NN) break;
            float vn = sqrtf(v[i][0] * v[i][0] + v[i][1] * v[i][1] +
                             v[i][2] * v[i][2] + 1e-8f);
            float in = v[i][0] * w[i][0] + v[i][1] * w[i][1] + v[i][2] * w[i][2];
            g_vnorm[n * HH + o] = vn;
            g_inner[n * HH + o] = in;
            g_muw[n * 3 * HH + o]          = w[i][0];
            g_muw[n * 3 * HH + HH + o]     = w[i][1];
            g_muw[n * 3 * HH + 2 * HH + o] = w[i][2];
        }
    }
}

// ---------------- scalar mix MLP + final update (Round-1 proven) ----------------
__global__ __launch_bounds__(256) void k_mix(
    const float* __restrict__ Wm1, const float* __restrict__ bm1,
    const float* __restrict__ Wm2, const float* __restrict__ bm2,
    float* __restrict__ qout, float* __restrict__ muout)
{
    __shared__ float sin_[16][H2];
    __shared__ float shid[16][H3];
    int tid = threadIdx.x;
    int n0 = blockIdx.x * 16;

    for (int i = tid; i < 16 * H2; i += 256) {
        int r = i >> 8;
        int c = i & 255;
        int n = n0 + r;
        float v = 0.f;
        if (n < NN) v = (c < HH) ? g_qmid[n * HH + c] : g_vnorm[n * HH + (c - HH)];
        sin_[r][c] = v;
    }
    __syncthreads();

    int rg = tid >> 6;
    int cg = tid & 63;
    int r0 = rg * 4;

    for (int pass = 0; pass < 2; ++pass) {
        int c0 = cg * 4 + pass * 256;
        if (c0 >= H3) break;
        float acc[4][4] = {};
        for (int k = 0; k < H2; ++k) {
            float4 w = *reinterpret_cast<const float4*>(&Wm1[k * H3 + c0]);
            #pragma unroll
            for (int i = 0; i < 4; ++i) {
                float s = sin_[r0 + i][k];
                acc[i][0] = fmaf(s, w.x, acc[i][0]);
                acc[i][1] = fmaf(s, w.y, acc[i][1]);
                acc[i][2] = fmaf(s, w.z, acc[i][2]);
                acc[i][3] = fmaf(s, w.w, acc[i][3]);
            }
        }
        #pragma unroll
        for (int i = 0; i < 4; ++i)
            #pragma unroll
            for (int j = 0; j < 4; ++j)
                shid[r0 + i][c0 + j] = silu_f(acc[i][j] + bm1[c0 + j]);
    }
    __syncthreads();

    for (int slot = tid; slot < 4 * HH; slot += 256) {
        int ng = slot >> 7;
        int o  = slot & 127;
        int rr0 = ng * 4;
        float aq[4] = {}, as[4] = {}, am[4] = {};
        for (int k = 0; k < H3; ++k) {
            float wq = Wm2[k * H3 + o];
            float ws = Wm2[k * H3 + HH + o];
            float wm = Wm2[k * H3 + 2 * HH + o];
            #pragma unroll
            for (int i = 0; i < 4; ++i) {
                float hv = shid[rr0 + i][k];
                aq[i] = fmaf(hv, wq, aq[i]);
                as[i] = fmaf(hv, ws, as[i]);
                am[i] = fmaf(hv, wm, am[i]);
            }
        }
        #pragma unroll
        for (int i = 0; i < 4; ++i) {
            int n = n0 + rr0 + i;
            if (n >= NN) break;
            float dq  = aq[i] + bm2[o];
            float dms = as[i] + bm2[HH + o];
            float dqm = am[i] + bm2[2 * HH + o];
            qout[n * HH + o] = g_qmid[n * HH + o] + dq + dqm * g_inner[n * HH + o];
            #pragma unroll
            for (int d = 0; d < 3; ++d) {
                int idx = n * 3 * HH + d * HH + o;
                muout[idx] = g_mumid[idx] + g_muw[idx] * dms;
            }
        }
    }
}

// ---------------- launch ----------------
extern "C" void kernel_launch(void* const* d_in, const int* in_sizes, int n_in,
                              void* d_out, int out_size)
{
    const float* q   = (const float*)d_in[0];
    const float* mu  = (const float*)d_in[1];
    const int*   ei  = (const int*)d_in[2];
    const float* rbf = (const float*)d_in[3];
    const float* uv  = (const float*)d_in[4];
    const float* cut = (const float*)d_in[5];
    const float* Wi1 = (const float*)d_in[6];
    const float* bi1 = (const float*)d_in[7];
    const float* Wi2 = (const float*)d_in[8];
    const float* bi2 = (const float*)d_in[9];
    const float* Wf1 = (const float*)d_in[10];
    const float* bf1 = (const float*)d_in[11];
    const float* Wf2 = (const float*)d_in[12];
    const float* bf2 = (const float*)d_in[13];
    const float* Wv  = (const float*)d_in[14];
    const float* Wm1 = (const float*)d_in[15];
    const float* bm1 = (const float*)d_in[16];
    const float* Wm2 = (const float*)d_in[17];
    const float* bm2 = (const float*)d_in[18];

    float* qout  = (float*)d_out;
    float* muout = qout + (size_t)NN * HH;

    // CSR build + weight split
    k_zero<<<(NN + 255) / 256, 256>>>();
    k_count<<<512, 256>>>(ei);
    k_splitb<<<((HH / 2) * H3 + 255) / 256, 256>>>(Wf2);
    k_scan<<<1, 1024>>>();
    k_fill<<<512, 256>>>(ei);

    // dense stages
    k_node_mlp<<<NN / 16, 256>>>(q, Wi1, bi1, Wi2, bi2);
    k_edge_filter<<<NE / 64, 256>>>(rbf, cut, Wf1, bf1, bf2);

    // message aggregation
    k_aggregate<<<NN, 128>>>(q, mu, ei, uv);

    // mixing
    k_equiv<<<(NN + 23) / 24, 256>>>(Wv);
    k_mix<<<(NN + 15) / 16, 256>>>(Wm1, bm1, Wm2, bm2, qout, muout);
}

// round 6
// speedup vs baseline: 1.8179x; 1.1142x over previous
#include <cuda_runtime.h>
#include <cuda_bf16.h>
#include <cuda_fp16.h>
#include <math.h>

#define NN 10000
#define NE 256000
#define HH 128
#define H2 256
#define H3 384
#define NR 20

typedef unsigned int u32;

// ---------------- scratch (static device globals; no allocation) ----------------
__device__ float  g_x[NN * H3];
__device__ __half g_filters[(size_t)NE * H3];      // fp16 filters (196 MB)
__device__ u32   g_bhp[(HH / 2) * H3];             // Wf2 hi (k-pair packed bf16x2)
__device__ u32   g_blp[(HH / 2) * H3];             // Wf2 lo
__device__ u32   g_i1h[(HH / 2) * H3];             // Wi1 hi
__device__ u32   g_i1l[(HH / 2) * H3];             // Wi1 lo
__device__ u32   g_i2h[(H3 / 2) * H3];             // Wi2 hi
__device__ u32   g_i2l[(H3 / 2) * H3];             // Wi2 lo
__device__ float g_qmid[NN * HH];
__device__ float g_mumid[NN * 3 * HH];
__device__ float g_vnorm[NN * HH];
__device__ float g_inner[NN * HH];
__device__ float g_muw[NN * 3 * HH];
__device__ int   g_count[NN];
__device__ int   g_off[NN + 1];
__device__ int   g_cursor[NN];
__device__ int   g_elist[NE];

__device__ __forceinline__ float silu_f(float x) {
    return x / (1.0f + __expf(-x));
}

__device__ __forceinline__ u32 pack_bf16x2(float lo, float hi) {
    u32 r;
    asm("cvt.rn.bf16x2.f32 %0, %1, %2;" : "=r"(r) : "f"(hi), "f"(lo));
    return r;
}

__device__ __forceinline__ void mma_bf16(float& c0, float& c1, float& c2, float& c3,
                                         u32 a0, u32 a1, u32 a2, u32 a3,
                                         u32 b0, u32 b1) {
    asm("mma.sync.aligned.m16n8k16.row.col.f32.bf16.bf16.f32 "
        "{%0,%1,%2,%3}, {%4,%5,%6,%7}, {%8,%9}, {%0,%1,%2,%3};"
        : "+f"(c0), "+f"(c1), "+f"(c2), "+f"(c3)
        : "r"(a0), "r"(a1), "r"(a2), "r"(a3), "r"(b0), "r"(b1));
}

// split + pack A (f32x2 -> bf16x2 hi, bf16x2 residual)
__device__ __forceinline__ void split_a(float2 f, u32& hi, u32& lo) {
    hi = pack_bf16x2(f.x, f.y);
    lo = pack_bf16x2(f.x - __uint_as_float(hi << 16),
                     f.y - __uint_as_float(hi & 0xFFFF0000u));
}

// ---------------- weight split (one-shot, tiny). W is [2*kpairs, 384] ----------------
__global__ void k_splitw(const float* __restrict__ W, u32* __restrict__ hi,
                         u32* __restrict__ lo, int kpairs) {
    int i = blockIdx.x * blockDim.x + threadIdx.x;
    if (i < kpairs * H3) {
        int p = i / H3, col = i % H3;
        float w0 = W[(2 * p) * H3 + col];
        float w1 = W[(2 * p + 1) * H3 + col];
        u32 h01 = pack_bf16x2(w0, w1);
        float h0 = __uint_as_float(h01 << 16);
        float h1 = __uint_as_float(h01 & 0xFFFF0000u);
        hi[i] = h01;
        lo[i] = pack_bf16x2(w0 - h0, w1 - h1);
    }
}

// ---------------- CSR build ----------------
__global__ void k_zero() {
    int i = blockIdx.x * blockDim.x + threadIdx.x;
    if (i < NN) g_count[i] = 0;
}

__global__ void k_count(const int* __restrict__ ei) {
    for (int e = blockIdx.x * blockDim.x + threadIdx.x; e < NE;
         e += gridDim.x * blockDim.x)
        atomicAdd(&g_count[ei[e]], 1);
}

__global__ __launch_bounds__(1024) void k_scan() {
    __shared__ int ps[1024];
    int tid = threadIdx.x;
    const int CH = (NN + 1023) / 1024;
    int base = tid * CH;
    int s = 0;
    for (int j = 0; j < CH; ++j) {
        int idx = base + j;
        if (idx < NN) s += g_count[idx];
    }
    ps[tid] = s;
    __syncthreads();
    for (int off = 1; off < 1024; off <<= 1) {
        int v = 0;
        if (tid >= off) v = ps[tid - off];
        __syncthreads();
        ps[tid] += v;
        __syncthreads();
    }
    int run = ps[tid] - s;
    for (int j = 0; j < CH; ++j) {
        int idx = base + j;
        if (idx < NN) {
            g_off[idx] = run;
            g_cursor[idx] = run;
            run += g_count[idx];
        }
    }
    if (tid == 1023) g_off[NN] = ps[1023];
}

__global__ void k_fill(const int* __restrict__ ei) {
    for (int e = blockIdx.x * blockDim.x + threadIdx.x; e < NE;
         e += gridDim.x * blockDim.x) {
        int t = ei[e];
        int pos = atomicAdd(&g_cursor[t], 1);
        g_elist[pos] = e;
    }
}

// ---------------- node inter MLP via bf16 split mma ----------------
// 32 nodes/block, 256 threads (8 warps). Warp: 2 row-tiles x 6 n-tiles.
#define SQP 132
#define SH2P 388
#define NODE_SMEM ((32 * SQP + 32 * SH2P) * 4)
__global__ __launch_bounds__(256) void k_node_mlp(
    const float* __restrict__ q,
    const float* __restrict__ b1, const float* __restrict__ b2)
{
    extern __shared__ float smn[];
    float* sq = smn;                 // [32][SQP]
    float* sh = smn + 32 * SQP;      // [32][SH2P]
    int tid = threadIdx.x;
    int n0 = blockIdx.x * 32;

    for (int i = tid; i < 32 * HH; i += 256) {
        int r = i >> 7, c = i & 127;
        int n = n0 + r;
        sq[r * SQP + c] = (n < NN) ? q[n * HH + c] : 0.f;
    }
    __syncthreads();

    int wid  = tid >> 5;
    int lane = tid & 31;
    int gid  = lane >> 2;
    int tig  = lane & 3;
    int nbase = wid * 48;

    // ---- phase 1: hidden = silu(q @ Wi1 + b1), K=128 ----
    {
        float acc[2][6][4];
        #pragma unroll
        for (int r = 0; r < 2; ++r)
            #pragma unroll
            for (int t = 0; t < 6; ++t)
                #pragma unroll
                for (int c = 0; c < 4; ++c) acc[r][t][c] = 0.f;

        #pragma unroll 1
        for (int k0 = 0; k0 < HH; k0 += 16) {
            int kp = k0 >> 1;
            u32 bh[6][2], bl[6][2];
            #pragma unroll
            for (int t = 0; t < 6; ++t) {
                int col = nbase + t * 8 + gid;
                int i0 = (kp + tig) * H3 + col;
                int i1 = (kp + 4 + tig) * H3 + col;
                bh[t][0] = __ldg(&g_i1h[i0]);
                bh[t][1] = __ldg(&g_i1h[i1]);
                bl[t][0] = __ldg(&g_i1l[i0]);
                bl[t][1] = __ldg(&g_i1l[i1]);
            }
            #pragma unroll
            for (int r = 0; r < 2; ++r) {
                int rb = r * 16;
                float2 f0 = *(const float2*)&sq[(rb + gid)     * SQP + k0 + 2 * tig];
                float2 f1 = *(const float2*)&sq[(rb + gid + 8) * SQP + k0 + 2 * tig];
                float2 f2 = *(const float2*)&sq[(rb + gid)     * SQP + k0 + 8 + 2 * tig];
                float2 f3 = *(const float2*)&sq[(rb + gid + 8) * SQP + k0 + 8 + 2 * tig];
                u32 ah0, al0, ah1, al1, ah2, al2, ah3, al3;
                split_a(f0, ah0, al0); split_a(f1, ah1, al1);
                split_a(f2, ah2, al2); split_a(f3, ah3, al3);
                #pragma unroll
                for (int t = 0; t < 6; ++t) {
                    mma_bf16(acc[r][t][0], acc[r][t][1], acc[r][t][2], acc[r][t][3],
                             ah0, ah1, ah2, ah3, bh[t][0], bh[t][1]);
                    mma_bf16(acc[r][t][0], acc[r][t][1], acc[r][t][2], acc[r][t][3],
                             al0, al1, al2, al3, bh[t][0], bh[t][1]);
                    mma_bf16(acc[r][t][0], acc[r][t][1], acc[r][t][2], acc[r][t][3],
                             ah0, ah1, ah2, ah3, bl[t][0], bl[t][1]);
                }
            }
        }
        #pragma unroll
        for (int r = 0; r < 2; ++r) {
            int row0 = r * 16 + gid;
            int row1 = row0 + 8;
            #pragma unroll
            for (int t = 0; t < 6; ++t) {
                int col = nbase + t * 8 + 2 * tig;
                float b0v = __ldg(&b1[col]);
                float b1v = __ldg(&b1[col + 1]);
                sh[row0 * SH2P + col]     = silu_f(acc[r][t][0] + b0v);
                sh[row0 * SH2P + col + 1] = silu_f(acc[r][t][1] + b1v);
                sh[row1 * SH2P + col]     = silu_f(acc[r][t][2] + b0v);
                sh[row1 * SH2P + col + 1] = silu_f(acc[r][t][3] + b1v);
            }
        }
    }
    __syncthreads();

    // ---- phase 2: x = hidden @ Wi2 + b2, K=384 ----
    {
        float acc[2][6][4];
        #pragma unroll
        for (int r = 0; r < 2; ++r)
            #pragma unroll
            for (int t = 0; t < 6; ++t)
                #pragma unroll
                for (int c = 0; c < 4; ++c) acc[r][t][c] = 0.f;

        #pragma unroll 1
        for (int k0 = 0; k0 < H3; k0 += 16) {
            int kp = k0 >> 1;
            u32 bh[6][2], bl[6][2];
            #pragma unroll
            for (int t = 0; t < 6; ++t) {
                int col = nbase + t * 8 + gid;
                int i0 = (kp + tig) * H3 + col;
                int i1 = (kp + 4 + tig) * H3 + col;
                bh[t][0] = __ldg(&g_i2h[i0]);
                bh[t][1] = __ldg(&g_i2h[i1]);
                bl[t][0] = __ldg(&g_i2l[i0]);
                bl[t][1] = __ldg(&g_i2l[i1]);
            }
            #pragma unroll
            for (int r = 0; r < 2; ++r) {
                int rb = r * 16;
                float2 f0 = *(const float2*)&sh[(rb + gid)     * SH2P + k0 + 2 * tig];
                float2 f1 = *(const float2*)&sh[(rb + gid + 8) * SH2P + k0 + 2 * tig];
                float2 f2 = *(const float2*)&sh[(rb + gid)     * SH2P + k0 + 8 + 2 * tig];
                float2 f3 = *(const float2*)&sh[(rb + gid + 8) * SH2P + k0 + 8 + 2 * tig];
                u32 ah0, al0, ah1, al1, ah2, al2, ah3, al3;
                split_a(f0, ah0, al0); split_a(f1, ah1, al1);
                split_a(f2, ah2, al2); split_a(f3, ah3, al3);
                #pragma unroll
                for (int t = 0; t < 6; ++t) {
                    mma_bf16(acc[r][t][0], acc[r][t][1], acc[r][t][2], acc[r][t][3],
                             ah0, ah1, ah2, ah3, bh[t][0], bh[t][1]);
                    mma_bf16(acc[r][t][0], acc[r][t][1], acc[r][t][2], acc[r][t][3],
                             al0, al1, al2, al3, bh[t][0], bh[t][1]);
                    mma_bf16(acc[r][t][0], acc[r][t][1], acc[r][t][2], acc[r][t][3],
                             ah0, ah1, ah2, ah3, bl[t][0], bl[t][1]);
                }
            }
        }
        #pragma unroll
        for (int r = 0; r < 2; ++r) {
            int row0 = r * 16 + gid;
            int row1 = row0 + 8;
            #pragma unroll
            for (int t = 0; t < 6; ++t) {
                int col = nbase + t * 8 + 2 * tig;
                float b0v = __ldg(&b2[col]);
                float b1v = __ldg(&b2[col + 1]);
                if (n0 + row0 < NN)
                    *(float2*)&g_x[(size_t)(n0 + row0) * H3 + col] =
                        make_float2(acc[r][t][0] + b0v, acc[r][t][1] + b1v);
                if (n0 + row1 < NN)
                    *(float2*)&g_x[(size_t)(n0 + row1) * H3 + col] =
                        make_float2(acc[r][t][2] + b0v, acc[r][t][3] + b1v);
            }
        }
    }
}

// ---------------- edge filter MLP: phase1 scalar, phase2 bf16 mma (3-split) ----------------
#define SHP 132
__global__ __launch_bounds__(256) void k_edge_filter(
    const float* __restrict__ rbf, const float* __restrict__ cut,
    const float* __restrict__ Wf1, const float* __restrict__ bf1,
    const float* __restrict__ bf2)
{
    __shared__ float srb[64][NR];
    __shared__ float scut[64];
    __shared__ __align__(16) float sh[64 * SHP];
    int tid = threadIdx.x;
    int e0 = blockIdx.x * 64;

    for (int i = tid; i < 64 * NR; i += 256)
        srb[i / NR][i % NR] = rbf[(e0 + i / NR) * NR + (i % NR)];
    if (tid < 64) scut[tid] = cut[e0 + tid];
    __syncthreads();

    // phase 1 (scalar, K=20)
    {
        int rg = tid >> 4;
        int cg = tid & 15;
        int r0 = rg * 4;
        for (int pass = 0; pass < 2; ++pass) {
            int c0 = cg * 4 + pass * 64;
            float acc[4][4] = {};
            for (int k = 0; k < NR; ++k) {
                float4 w = *reinterpret_cast<const float4*>(&Wf1[k * HH + c0]);
                #pragma unroll
                for (int i = 0; i < 4; ++i) {
                    float s = srb[r0 + i][k];
                    acc[i][0] = fmaf(s, w.x, acc[i][0]);
                    acc[i][1] = fmaf(s, w.y, acc[i][1]);
                    acc[i][2] = fmaf(s, w.z, acc[i][2]);
                    acc[i][3] = fmaf(s, w.w, acc[i][3]);
                }
            }
            #pragma unroll
            for (int i = 0; i < 4; ++i)
                #pragma unroll
                for (int j = 0; j < 4; ++j)
                    sh[(r0 + i) * SHP + c0 + j] = silu_f(acc[i][j] + bf1[c0 + j]);
        }
    }
    __syncthreads();

    // phase 2: bf16 split mma
    int wid  = tid >> 5;
    int lane = tid & 31;
    int gid  = lane >> 2;
    int tig  = lane & 3;
    int nbase = wid * 48;

    float acc[4][6][4];
    #pragma unroll
    for (int r = 0; r < 4; ++r)
        #pragma unroll
        for (int t = 0; t < 6; ++t)
            #pragma unroll
            for (int c = 0; c < 4; ++c) acc[r][t][c] = 0.f;

    #pragma unroll 1
    for (int k0 = 0; k0 < HH; k0 += 16) {
        int kp = k0 >> 1;
        u32 bh[6][2], bl[6][2];
        #pragma unroll
        for (int t = 0; t < 6; ++t) {
            int col = nbase + t * 8 + gid;
            int i0 = (kp + tig) * H3 + col;
            int i1 = (kp + 4 + tig) * H3 + col;
            bh[t][0] = __ldg(&g_bhp[i0]);
            bh[t][1] = __ldg(&g_bhp[i1]);
            bl[t][0] = __ldg(&g_blp[i0]);
            bl[t][1] = __ldg(&g_blp[i1]);
        }
        #pragma unroll
        for (int r = 0; r < 4; ++r) {
            int rb = r * 16;
            float2 f0 = *(const float2*)&sh[(rb + gid)     * SHP + k0 + 2 * tig];
            float2 f1 = *(const float2*)&sh[(rb + gid + 8) * SHP + k0 + 2 * tig];
            float2 f2 = *(const float2*)&sh[(rb + gid)     * SHP + k0 + 8 + 2 * tig];
            float2 f3 = *(const float2*)&sh[(rb + gid + 8) * SHP + k0 + 8 + 2 * tig];
            u32 ah0, al0, ah1, al1, ah2, al2, ah3, al3;
            split_a(f0, ah0, al0); split_a(f1, ah1, al1);
            split_a(f2, ah2, al2); split_a(f3, ah3, al3);
            #pragma unroll
            for (int t = 0; t < 6; ++t) {
                mma_bf16(acc[r][t][0], acc[r][t][1], acc[r][t][2], acc[r][t][3],
                         ah0, ah1, ah2, ah3, bh[t][0], bh[t][1]);
                mma_bf16(acc[r][t][0], acc[r][t][1], acc[r][t][2], acc[r][t][3],
                         al0, al1, al2, al3, bh[t][0], bh[t][1]);
                mma_bf16(acc[r][t][0], acc[r][t][1], acc[r][t][2], acc[r][t][3],
                         ah0, ah1, ah2, ah3, bl[t][0], bl[t][1]);
            }
        }
    }

    // epilogue: bias + cutoff, store fp16
    #pragma unroll
    for (int r = 0; r < 4; ++r) {
        int row0 = r * 16 + gid;
        int row1 = row0 + 8;
        float c0v = scut[row0];
        float c1v = scut[row1];
        #pragma unroll
        for (int t = 0; t < 6; ++t) {
            int col = nbase + t * 8 + 2 * tig;
            float b0v = bf2[col];
            float b1v = bf2[col + 1];
            __half2 v0 = __floats2half2_rn((acc[r][t][0] + b0v) * c0v,
                                           (acc[r][t][1] + b1v) * c0v);
            __half2 v1 = __floats2half2_rn((acc[r][t][2] + b0v) * c1v,
                                           (acc[r][t][3] + b1v) * c1v);
            *(__half2*)&g_filters[(size_t)(e0 + row0) * H3 + col] = v0;
            *(__half2*)&g_filters[(size_t)(e0 + row1) * H3 + col] = v1;
        }
    }
}

// ---------------- pull aggregation (CSR) -> qmid, mumid ----------------
__global__ __launch_bounds__(128) void k_aggregate(
    const float* __restrict__ q, const float* __restrict__ mu,
    const int* __restrict__ ei, const float* __restrict__ uv)
{
    int n = blockIdx.x;
    int h = threadIdx.x;
    int beg = g_off[n], end = g_off[n + 1];
    float qa = 0.f, m0 = 0.f, m1 = 0.f, m2 = 0.f;
    for (int i = beg; i < end; ++i) {
        int e = g_elist[i];
        int s = ei[NE + e];
        const __half* f = &g_filters[(size_t)e * H3];
        float fq = __half2float(f[h]);
        float fr = __half2float(f[HH + h]);
        float fm = __half2float(f[2 * HH + h]);
        const float* xs = &g_x[s * H3];
        float xq = xs[h] * fq;
        float xr = xs[HH + h] * fr;
        float xm = xs[2 * HH + h] * fm;
        float u0 = uv[e * 3 + 0], u1 = uv[e * 3 + 1], u2 = uv[e * 3 + 2];
        const float* ms = &mu[s * 3 * HH];
        qa += xq;
        m0 = fmaf(u0, xr, fmaf(ms[h],          xm, m0));
        m1 = fmaf(u1, xr, fmaf(ms[HH + h],     xm, m1));
        m2 = fmaf(u2, xr, fmaf(ms[2 * HH + h], xm, m2));
    }
    g_qmid[n * HH + h] = q[n * HH + h] + qa;
    g_mumid[n * 3 * HH + h]          = mu[n * 3 * HH + h] + m0;
    g_mumid[n * 3 * HH + HH + h]     = mu[n * 3 * HH + HH + h] + m1;
    g_mumid[n * 3 * HH + 2 * HH + h] = mu[n * 3 * HH + 2 * HH + h] + m2;
}

// ---------------- equivariant linear: vnorm, inner, mu_w ----------------
__global__ __launch_bounds__(256) void k_equiv(const float* __restrict__ Wvec)
{
    __shared__ float smu[24][3 * HH];
    int tid = threadIdx.x;
    int n0 = blockIdx.x * 24;

    for (int i = tid; i < 24 * 3 * HH; i += 256) {
        int r = i / (3 * HH);
        int c = i % (3 * HH);
        int n = n0 + r;
        smu[r][c] = (n < NN) ? g_mumid[n * 3 * HH + c] : 0.f;
    }
    __syncthreads();

    for (int slot = tid; slot < 6 * HH; slot += 256) {
        int ng = slot >> 7;
        int o  = slot & 127;
        int r0 = ng * 4;
        float v[4][3] = {};
        float w[4][3] = {};
        for (int k = 0; k < HH; ++k) {
            float wv = Wvec[k * H2 + o];
            float ww = Wvec[k * H2 + HH + o];
            #pragma unroll
            for (int i = 0; i < 4; ++i)
                #pragma unroll
                for (int d = 0; d < 3; ++d) {
                    float m = smu[r0 + i][d * HH + k];
                    v[i][d] = fmaf(m, wv, v[i][d]);
                    w[i][d] = fmaf(m, ww, w[i][d]);
                }
        }
        #pragma unroll
        for (int i = 0; i < 4; ++i) {
            int n = n0 + r0 + i;
            if (n >= NN) break;
            float vn = sqrtf(v[i][0] * v[i][0] + v[i][1] * v[i][1] +
                             v[i][2] * v[i][2] + 1e-8f);
            float in = v[i][0] * w[i][0] + v[i][1] * w[i][1] + v[i][2] * w[i][2];
            g_vnorm[n * HH + o] = vn;
            g_inner[n * HH + o] = in;
            g_muw[n * 3 * HH + o]          = w[i][0];
            g_muw[n * 3 * HH + HH + o]     = w[i][1];
            g_muw[n * 3 * HH + 2 * HH + o] = w[i][2];
        }
    }
}

// ---------------- scalar mix MLP + final update (Round-1 proven) ----------------
__global__ __launch_bounds__(256) void k_mix(
    const float* __restrict__ Wm1, const float* __restrict__ bm1,
    const float* __restrict__ Wm2, const float* __restrict__ bm2,
    float* __restrict__ qout, float* __restrict__ muout)
{
    __shared__ float sin_[16][H2];
    __shared__ float shid[16][H3];
    int tid = threadIdx.x;
    int n0 = blockIdx.x * 16;

    for (int i = tid; i < 16 * H2; i += 256) {
        int r = i >> 8;
        int c = i & 255;
        int n = n0 + r;
        float v = 0.f;
        if (n < NN) v = (c < HH) ? g_qmid[n * HH + c] : g_vnorm[n * HH + (c - HH)];
        sin_[r][c] = v;
    }
    __syncthreads();

    int rg = tid >> 6;
    int cg = tid & 63;
    int r0 = rg * 4;

    for (int pass = 0; pass < 2; ++pass) {
        int c0 = cg * 4 + pass * 256;
        if (c0 >= H3) break;
        float acc[4][4] = {};
        for (int k = 0; k < H2; ++k) {
            float4 w = *reinterpret_cast<const float4*>(&Wm1[k * H3 + c0]);
            #pragma unroll
            for (int i = 0; i < 4; ++i) {
                float s = sin_[r0 + i][k];
                acc[i][0] = fmaf(s, w.x, acc[i][0]);
                acc[i][1] = fmaf(s, w.y, acc[i][1]);
                acc[i][2] = fmaf(s, w.z, acc[i][2]);
                acc[i][3] = fmaf(s, w.w, acc[i][3]);
            }
        }
        #pragma unroll
        for (int i = 0; i < 4; ++i)
            #pragma unroll
            for (int j = 0; j < 4; ++j)
                shid[r0 + i][c0 + j] = silu_f(acc[i][j] + bm1[c0 + j]);
    }
    __syncthreads();

    for (int slot = tid; slot < 4 * HH; slot += 256) {
        int ng = slot >> 7;
        int o  = slot & 127;
        int rr0 = ng * 4;
        float aq[4] = {}, as[4] = {}, am[4] = {};
        for (int k = 0; k < H3; ++k) {
            float wq = Wm2[k * H3 + o];
            float ws = Wm2[k * H3 + HH + o];
            float wm = Wm2[k * H3 + 2 * HH + o];
            #pragma unroll
            for (int i = 0; i < 4; ++i) {
                float hv = shid[rr0 + i][k];
                aq[i] = fmaf(hv, wq, aq[i]);
                as[i] = fmaf(hv, ws, as[i]);
                am[i] = fmaf(hv, wm, am[i]);
            }
        }
        #pragma unroll
        for (int i = 0; i < 4; ++i) {
            int n = n0 + rr0 + i;
            if (n >= NN) break;
            float dq  = aq[i] + bm2[o];
            float dms = as[i] + bm2[HH + o];
            float dqm = am[i] + bm2[2 * HH + o];
            qout[n * HH + o] = g_qmid[n * HH + o] + dq + dqm * g_inner[n * HH + o];
            #pragma unroll
            for (int d = 0; d < 3; ++d) {
                int idx = n * 3 * HH + d * HH + o;
                muout[idx] = g_mumid[idx] + g_muw[idx] * dms;
            }
        }
    }
}

// ---------------- launch ----------------
extern "C" void kernel_launch(void* const* d_in, const int* in_sizes, int n_in,
                              void* d_out, int out_size)
{
    const float* q   = (const float*)d_in[0];
    const float* mu  = (const float*)d_in[1];
    const int*   ei  = (const int*)d_in[2];
    const float* rbf = (const float*)d_in[3];
    const float* uv  = (const float*)d_in[4];
    const float* cut = (const float*)d_in[5];
    const float* Wi1 = (const float*)d_in[6];
    const float* bi1 = (const float*)d_in[7];
    const float* Wi2 = (const float*)d_in[8];
    const float* bi2 = (const float*)d_in[9];
    const float* Wf1 = (const float*)d_in[10];
    const float* bf1 = (const float*)d_in[11];
    const float* Wf2 = (const float*)d_in[12];
    const float* bf2 = (const float*)d_in[13];
    const float* Wv  = (const float*)d_in[14];
    const float* Wm1 = (const float*)d_in[15];
    const float* bm1 = (const float*)d_in[16];
    const float* Wm2 = (const float*)d_in[17];
    const float* bm2 = (const float*)d_in[18];

    float* qout  = (float*)d_out;
    float* muout = qout + (size_t)NN * HH;

    static u32* hp = nullptr;
    cudaFuncSetAttribute(k_node_mlp, cudaFuncAttributeMaxDynamicSharedMemorySize, NODE_SMEM);
    (void)hp;

    // CSR build + weight splits
    k_zero<<<(NN + 255) / 256, 256>>>();
    k_count<<<512, 256>>>(ei);
    {
        u32 *d_bhp, *d_blp, *d_i1h, *d_i1l, *d_i2h, *d_i2l;
        cudaGetSymbolAddress((void**)&d_bhp, g_bhp);
        cudaGetSymbolAddress((void**)&d_blp, g_blp);
        cudaGetSymbolAddress((void**)&d_i1h, g_i1h);
        cudaGetSymbolAddress((void**)&d_i1l, g_i1l);
        cudaGetSymbolAddress((void**)&d_i2h, g_i2h);
        cudaGetSymbolAddress((void**)&d_i2l, g_i2l);
        k_splitw<<<((HH / 2) * H3 + 255) / 256, 256>>>(Wf2, d_bhp, d_blp, HH / 2);
        k_splitw<<<((HH / 2) * H3 + 255) / 256, 256>>>(Wi1, d_i1h, d_i1l, HH / 2);
        k_splitw<<<((H3 / 2) * H3 + 255) / 256, 256>>>(Wi2, d_i2h, d_i2l, H3 / 2);
    }
    k_scan<<<1, 1024>>>();
    k_fill<<<512, 256>>>(ei);

    // dense stages
    k_node_mlp<<<(NN + 31) / 32, 256, NODE_SMEM>>>(q, bi1, bi2);
    k_edge_filter<<<NE / 64, 256>>>(rbf, cut, Wf1, bf1, bf2);

    // message aggregation
    k_aggregate<<<NN, 128>>>(q, mu, ei, uv);

    // mixing
    k_equiv<<<(NN + 23) / 24, 256>>>(Wv);
    k_mix<<<(NN + 15) / 16, 256>>>(Wm1, bm1, Wm2, bm2, qout, muout);
}

// round 7
// speedup vs baseline: 2.2612x; 1.2438x over previous
#include <cuda_runtime.h>
#include <cuda_bf16.h>
#include <cuda_fp16.h>
#include <math.h>

#define NN 10000
#define NE 256000
#define HH 128
#define H2 256
#define H3 384
#define NR 20

typedef unsigned int u32;

// ---------------- scratch (static device globals; no allocation) ----------------
__device__ float  g_x[NN * H3];
__device__ __half g_filters[(size_t)NE * H3];      // fp16 filters (196 MB)
__device__ u32   g_bhp[(HH / 2) * H3];             // Wf2 hi (k-pair packed bf16x2)
__device__ u32   g_blp[(HH / 2) * H3];             // Wf2 lo
__device__ u32   g_i1h[(HH / 2) * H3];             // Wi1 hi
__device__ u32   g_i1l[(HH / 2) * H3];             // Wi1 lo
__device__ u32   g_i2h[(H3 / 2) * H3];             // Wi2 hi
__device__ u32   g_i2l[(H3 / 2) * H3];             // Wi2 lo
__device__ u32   g_vch[(HH / 2) * H2];             // Wvec hi
__device__ u32   g_vcl[(HH / 2) * H2];             // Wvec lo
__device__ u32   g_m1h[(H2 / 2) * H3];             // Wm1 hi
__device__ u32   g_m1l[(H2 / 2) * H3];             // Wm1 lo
__device__ u32   g_m2h[(H3 / 2) * H3];             // Wm2 hi
__device__ u32   g_m2l[(H3 / 2) * H3];             // Wm2 lo
__device__ float g_qmid[NN * HH];
__device__ float g_mumid[NN * 3 * HH];
__device__ float g_vnorm[NN * HH];
__device__ float g_inner[NN * HH];
__device__ float g_muw[NN * 3 * HH];
__device__ int   g_count[NN];
__device__ int   g_off[NN + 1];
__device__ int   g_cursor[NN];
__device__ int   g_elist[NE];

__device__ __forceinline__ float silu_f(float x) {
    return x / (1.0f + __expf(-x));
}

__device__ __forceinline__ u32 pack_bf16x2(float lo, float hi) {
    u32 r;
    asm("cvt.rn.bf16x2.f32 %0, %1, %2;" : "=r"(r) : "f"(hi), "f"(lo));
    return r;
}

__device__ __forceinline__ void mma_bf16(float& c0, float& c1, float& c2, float& c3,
                                         u32 a0, u32 a1, u32 a2, u32 a3,
                                         u32 b0, u32 b1) {
    asm("mma.sync.aligned.m16n8k16.row.col.f32.bf16.bf16.f32 "
        "{%0,%1,%2,%3}, {%4,%5,%6,%7}, {%8,%9}, {%0,%1,%2,%3};"
        : "+f"(c0), "+f"(c1), "+f"(c2), "+f"(c3)
        : "r"(a0), "r"(a1), "r"(a2), "r"(a3), "r"(b0), "r"(b1));
}

__device__ __forceinline__ void split_a(float2 f, u32& hi, u32& lo) {
    hi = pack_bf16x2(f.x, f.y);
    lo = pack_bf16x2(f.x - __uint_as_float(hi << 16),
                     f.y - __uint_as_float(hi & 0xFFFF0000u));
}

// ---------------- weight split (one-shot, tiny). W is [2*kpairs, width] ----------------
__global__ void k_splitw(const float* __restrict__ W, u32* __restrict__ hi,
                         u32* __restrict__ lo, int kpairs, int width) {
    int i = blockIdx.x * blockDim.x + threadIdx.x;
    if (i < kpairs * width) {
        int p = i / width, col = i % width;
        float w0 = W[(2 * p) * width + col];
        float w1 = W[(2 * p + 1) * width + col];
        u32 h01 = pack_bf16x2(w0, w1);
        float h0 = __uint_as_float(h01 << 16);
        float h1 = __uint_as_float(h01 & 0xFFFF0000u);
        hi[i] = h01;
        lo[i] = pack_bf16x2(w0 - h0, w1 - h1);
    }
}

// ---------------- CSR build ----------------
__global__ void k_zero() {
    int i = blockIdx.x * blockDim.x + threadIdx.x;
    if (i < NN) g_count[i] = 0;
}

__global__ void k_count(const int* __restrict__ ei) {
    for (int e = blockIdx.x * blockDim.x + threadIdx.x; e < NE;
         e += gridDim.x * blockDim.x)
        atomicAdd(&g_count[ei[e]], 1);
}

__global__ __launch_bounds__(1024) void k_scan() {
    __shared__ int ps[1024];
    int tid = threadIdx.x;
    const int CH = (NN + 1023) / 1024;
    int base = tid * CH;
    int s = 0;
    for (int j = 0; j < CH; ++j) {
        int idx = base + j;
        if (idx < NN) s += g_count[idx];
    }
    ps[tid] = s;
    __syncthreads();
    for (int off = 1; off < 1024; off <<= 1) {
        int v = 0;
        if (tid >= off) v = ps[tid - off];
        __syncthreads();
        ps[tid] += v;
        __syncthreads();
    }
    int run = ps[tid] - s;
    for (int j = 0; j < CH; ++j) {
        int idx = base + j;
        if (idx < NN) {
            g_off[idx] = run;
            g_cursor[idx] = run;
            run += g_count[idx];
        }
    }
    if (tid == 1023) g_off[NN] = ps[1023];
}

__global__ void k_fill(const int* __restrict__ ei) {
    for (int e = blockIdx.x * blockDim.x + threadIdx.x; e < NE;
         e += gridDim.x * blockDim.x) {
        int t = ei[e];
        int pos = atomicAdd(&g_cursor[t], 1);
        g_elist[pos] = e;
    }
}

// ---------------- node inter MLP via bf16 split mma (proven) ----------------
#define SQP 132
#define SH2P 388
#define NODE_SMEM ((32 * SQP + 32 * SH2P) * 4)
__global__ __launch_bounds__(256) void k_node_mlp(
    const float* __restrict__ q,
    const float* __restrict__ b1, const float* __restrict__ b2)
{
    extern __shared__ float smn[];
    float* sq = smn;
    float* sh = smn + 32 * SQP;
    int tid = threadIdx.x;
    int n0 = blockIdx.x * 32;

    for (int i = tid; i < 32 * HH; i += 256) {
        int r = i >> 7, c = i & 127;
        int n = n0 + r;
        sq[r * SQP + c] = (n < NN) ? q[n * HH + c] : 0.f;
    }
    __syncthreads();

    int wid  = tid >> 5;
    int lane = tid & 31;
    int gid  = lane >> 2;
    int tig  = lane & 3;
    int nbase = wid * 48;

    {
        float acc[2][6][4];
        #pragma unroll
        for (int r = 0; r < 2; ++r)
            #pragma unroll
            for (int t = 0; t < 6; ++t)
                #pragma unroll
                for (int c = 0; c < 4; ++c) acc[r][t][c] = 0.f;

        #pragma unroll 1
        for (int k0 = 0; k0 < HH; k0 += 16) {
            int kp = k0 >> 1;
            u32 bh[6][2], bl[6][2];
            #pragma unroll
            for (int t = 0; t < 6; ++t) {
                int col = nbase + t * 8 + gid;
                int i0 = (kp + tig) * H3 + col;
                int i1 = (kp + 4 + tig) * H3 + col;
                bh[t][0] = __ldg(&g_i1h[i0]);
                bh[t][1] = __ldg(&g_i1h[i1]);
                bl[t][0] = __ldg(&g_i1l[i0]);
                bl[t][1] = __ldg(&g_i1l[i1]);
            }
            #pragma unroll
            for (int r = 0; r < 2; ++r) {
                int rb = r * 16;
                float2 f0 = *(const float2*)&sq[(rb + gid)     * SQP + k0 + 2 * tig];
                float2 f1 = *(const float2*)&sq[(rb + gid + 8) * SQP + k0 + 2 * tig];
                float2 f2 = *(const float2*)&sq[(rb + gid)     * SQP + k0 + 8 + 2 * tig];
                float2 f3 = *(const float2*)&sq[(rb + gid + 8) * SQP + k0 + 8 + 2 * tig];
                u32 ah0, al0, ah1, al1, ah2, al2, ah3, al3;
                split_a(f0, ah0, al0); split_a(f1, ah1, al1);
                split_a(f2, ah2, al2); split_a(f3, ah3, al3);
                #pragma unroll
                for (int t = 0; t < 6; ++t) {
                    mma_bf16(acc[r][t][0], acc[r][t][1], acc[r][t][2], acc[r][t][3],
                             ah0, ah1, ah2, ah3, bh[t][0], bh[t][1]);
                    mma_bf16(acc[r][t][0], acc[r][t][1], acc[r][t][2], acc[r][t][3],
                             al0, al1, al2, al3, bh[t][0], bh[t][1]);
                    mma_bf16(acc[r][t][0], acc[r][t][1], acc[r][t][2], acc[r][t][3],
                             ah0, ah1, ah2, ah3, bl[t][0], bl[t][1]);
                }
            }
        }
        #pragma unroll
        for (int r = 0; r < 2; ++r) {
            int row0 = r * 16 + gid;
            int row1 = row0 + 8;
            #pragma unroll
            for (int t = 0; t < 6; ++t) {
                int col = nbase + t * 8 + 2 * tig;
                float b0v = __ldg(&b1[col]);
                float b1v = __ldg(&b1[col + 1]);
                sh[row0 * SH2P + col]     = silu_f(acc[r][t][0] + b0v);
                sh[row0 * SH2P + col + 1] = silu_f(acc[r][t][1] + b1v);
                sh[row1 * SH2P + col]     = silu_f(acc[r][t][2] + b0v);
                sh[row1 * SH2P + col + 1] = silu_f(acc[r][t][3] + b1v);
            }
        }
    }
    __syncthreads();

    {
        float acc[2][6][4];
        #pragma unroll
        for (int r = 0; r < 2; ++r)
            #pragma unroll
            for (int t = 0; t < 6; ++t)
                #pragma unroll
                for (int c = 0; c < 4; ++c) acc[r][t][c] = 0.f;

        #pragma unroll 1
        for (int k0 = 0; k0 < H3; k0 += 16) {
            int kp = k0 >> 1;
            u32 bh[6][2], bl[6][2];
            #pragma unroll
            for (int t = 0; t < 6; ++t) {
                int col = nbase + t * 8 + gid;
                int i0 = (kp + tig) * H3 + col;
                int i1 = (kp + 4 + tig) * H3 + col;
                bh[t][0] = __ldg(&g_i2h[i0]);
                bh[t][1] = __ldg(&g_i2h[i1]);
                bl[t][0] = __ldg(&g_i2l[i0]);
                bl[t][1] = __ldg(&g_i2l[i1]);
            }
            #pragma unroll
            for (int r = 0; r < 2; ++r) {
                int rb = r * 16;
                float2 f0 = *(const float2*)&sh[(rb + gid)     * SH2P + k0 + 2 * tig];
                float2 f1 = *(const float2*)&sh[(rb + gid + 8) * SH2P + k0 + 2 * tig];
                float2 f2 = *(const float2*)&sh[(rb + gid)     * SH2P + k0 + 8 + 2 * tig];
                float2 f3 = *(const float2*)&sh[(rb + gid + 8) * SH2P + k0 + 8 + 2 * tig];
                u32 ah0, al0, ah1, al1, ah2, al2, ah3, al3;
                split_a(f0, ah0, al0); split_a(f1, ah1, al1);
                split_a(f2, ah2, al2); split_a(f3, ah3, al3);
                #pragma unroll
                for (int t = 0; t < 6; ++t) {
                    mma_bf16(acc[r][t][0], acc[r][t][1], acc[r][t][2], acc[r][t][3],
                             ah0, ah1, ah2, ah3, bh[t][0], bh[t][1]);
                    mma_bf16(acc[r][t][0], acc[r][t][1], acc[r][t][2], acc[r][t][3],
                             al0, al1, al2, al3, bh[t][0], bh[t][1]);
                    mma_bf16(acc[r][t][0], acc[r][t][1], acc[r][t][2], acc[r][t][3],
                             ah0, ah1, ah2, ah3, bl[t][0], bl[t][1]);
                }
            }
        }
        #pragma unroll
        for (int r = 0; r < 2; ++r) {
            int row0 = r * 16 + gid;
            int row1 = row0 + 8;
            #pragma unroll
            for (int t = 0; t < 6; ++t) {
                int col = nbase + t * 8 + 2 * tig;
                float b0v = __ldg(&b2[col]);
                float b1v = __ldg(&b2[col + 1]);
                if (n0 + row0 < NN)
                    *(float2*)&g_x[(size_t)(n0 + row0) * H3 + col] =
                        make_float2(acc[r][t][0] + b0v, acc[r][t][1] + b1v);
                if (n0 + row1 < NN)
                    *(float2*)&g_x[(size_t)(n0 + row1) * H3 + col] =
                        make_float2(acc[r][t][2] + b0v, acc[r][t][3] + b1v);
            }
        }
    }
}

// ---------------- edge filter MLP (proven) ----------------
#define SHP 132
__global__ __launch_bounds__(256) void k_edge_filter(
    const float* __restrict__ rbf, const float* __restrict__ cut,
    const float* __restrict__ Wf1, const float* __restrict__ bf1,
    const float* __restrict__ bf2)
{
    __shared__ float srb[64][NR];
    __shared__ float scut[64];
    __shared__ __align__(16) float sh[64 * SHP];
    int tid = threadIdx.x;
    int e0 = blockIdx.x * 64;

    for (int i = tid; i < 64 * NR; i += 256)
        srb[i / NR][i % NR] = rbf[(e0 + i / NR) * NR + (i % NR)];
    if (tid < 64) scut[tid] = cut[e0 + tid];
    __syncthreads();

    {
        int rg = tid >> 4;
        int cg = tid & 15;
        int r0 = rg * 4;
        for (int pass = 0; pass < 2; ++pass) {
            int c0 = cg * 4 + pass * 64;
            float acc[4][4] = {};
            for (int k = 0; k < NR; ++k) {
                float4 w = *reinterpret_cast<const float4*>(&Wf1[k * HH + c0]);
                #pragma unroll
                for (int i = 0; i < 4; ++i) {
                    float s = srb[r0 + i][k];
                    acc[i][0] = fmaf(s, w.x, acc[i][0]);
                    acc[i][1] = fmaf(s, w.y, acc[i][1]);
                    acc[i][2] = fmaf(s, w.z, acc[i][2]);
                    acc[i][3] = fmaf(s, w.w, acc[i][3]);
                }
            }
            #pragma unroll
            for (int i = 0; i < 4; ++i)
                #pragma unroll
                for (int j = 0; j < 4; ++j)
                    sh[(r0 + i) * SHP + c0 + j] = silu_f(acc[i][j] + bf1[c0 + j]);
        }
    }
    __syncthreads();

    int wid  = tid >> 5;
    int lane = tid & 31;
    int gid  = lane >> 2;
    int tig  = lane & 3;
    int nbase = wid * 48;

    float acc[4][6][4];
    #pragma unroll
    for (int r = 0; r < 4; ++r)
        #pragma unroll
        for (int t = 0; t < 6; ++t)
            #pragma unroll
            for (int c = 0; c < 4; ++c) acc[r][t][c] = 0.f;

    #pragma unroll 1
    for (int k0 = 0; k0 < HH; k0 += 16) {
        int kp = k0 >> 1;
        u32 bh[6][2], bl[6][2];
        #pragma unroll
        for (int t = 0; t < 6; ++t) {
            int col = nbase + t * 8 + gid;
            int i0 = (kp + tig) * H3 + col;
            int i1 = (kp + 4 + tig) * H3 + col;
            bh[t][0] = __ldg(&g_bhp[i0]);
            bh[t][1] = __ldg(&g_bhp[i1]);
            bl[t][0] = __ldg(&g_blp[i0]);
            bl[t][1] = __ldg(&g_blp[i1]);
        }
        #pragma unroll
        for (int r = 0; r < 4; ++r) {
            int rb = r * 16;
            float2 f0 = *(const float2*)&sh[(rb + gid)     * SHP + k0 + 2 * tig];
            float2 f1 = *(const float2*)&sh[(rb + gid + 8) * SHP + k0 + 2 * tig];
            float2 f2 = *(const float2*)&sh[(rb + gid)     * SHP + k0 + 8 + 2 * tig];
            float2 f3 = *(const float2*)&sh[(rb + gid + 8) * SHP + k0 + 8 + 2 * tig];
            u32 ah0, al0, ah1, al1, ah2, al2, ah3, al3;
            split_a(f0, ah0, al0); split_a(f1, ah1, al1);
            split_a(f2, ah2, al2); split_a(f3, ah3, al3);
            #pragma unroll
            for (int t = 0; t < 6; ++t) {
                mma_bf16(acc[r][t][0], acc[r][t][1], acc[r][t][2], acc[r][t][3],
                         ah0, ah1, ah2, ah3, bh[t][0], bh[t][1]);
                mma_bf16(acc[r][t][0], acc[r][t][1], acc[r][t][2], acc[r][t][3],
                         al0, al1, al2, al3, bh[t][0], bh[t][1]);
                mma_bf16(acc[r][t][0], acc[r][t][1], acc[r][t][2], acc[r][t][3],
                         ah0, ah1, ah2, ah3, bl[t][0], bl[t][1]);
            }
        }
    }

    #pragma unroll
    for (int r = 0; r < 4; ++r) {
        int row0 = r * 16 + gid;
        int row1 = row0 + 8;
        float c0v = scut[row0];
        float c1v = scut[row1];
        #pragma unroll
        for (int t = 0; t < 6; ++t) {
            int col = nbase + t * 8 + 2 * tig;
            float b0v = bf2[col];
            float b1v = bf2[col + 1];
            __half2 v0 = __floats2half2_rn((acc[r][t][0] + b0v) * c0v,
                                           (acc[r][t][1] + b1v) * c0v);
            __half2 v1 = __floats2half2_rn((acc[r][t][2] + b0v) * c1v,
                                           (acc[r][t][3] + b1v) * c1v);
            *(__half2*)&g_filters[(size_t)(e0 + row0) * H3 + col] = v0;
            *(__half2*)&g_filters[(size_t)(e0 + row1) * H3 + col] = v1;
        }
    }
}

// ---------------- pull aggregation (CSR) -> qmid, mumid ----------------
__global__ __launch_bounds__(128) void k_aggregate(
    const float* __restrict__ q, const float* __restrict__ mu,
    const int* __restrict__ ei, const float* __restrict__ uv)
{
    int n = blockIdx.x;
    int h = threadIdx.x;
    int beg = g_off[n], end = g_off[n + 1];
    float qa = 0.f, m0 = 0.f, m1 = 0.f, m2 = 0.f;
    for (int i = beg; i < end; ++i) {
        int e = g_elist[i];
        int s = ei[NE + e];
        const __half* f = &g_filters[(size_t)e * H3];
        float fq = __half2float(f[h]);
        float fr = __half2float(f[HH + h]);
        float fm = __half2float(f[2 * HH + h]);
        const float* xs = &g_x[s * H3];
        float xq = xs[h] * fq;
        float xr = xs[HH + h] * fr;
        float xm = xs[2 * HH + h] * fm;
        float u0 = uv[e * 3 + 0], u1 = uv[e * 3 + 1], u2 = uv[e * 3 + 2];
        const float* ms = &mu[s * 3 * HH];
        qa += xq;
        m0 = fmaf(u0, xr, fmaf(ms[h],          xm, m0));
        m1 = fmaf(u1, xr, fmaf(ms[HH + h],     xm, m1));
        m2 = fmaf(u2, xr, fmaf(ms[2 * HH + h], xm, m2));
    }
    g_qmid[n * HH + h] = q[n * HH + h] + qa;
    g_mumid[n * 3 * HH + h]          = mu[n * 3 * HH + h] + m0;
    g_mumid[n * 3 * HH + HH + h]     = mu[n * 3 * HH + HH + h] + m1;
    g_mumid[n * 3 * HH + 2 * HH + h] = mu[n * 3 * HH + 2 * HH + h] + m2;
}

// ---------------- equivariant linear via bf16 split mma ----------------
// 16 nodes/block = 48 mu-rows. 8 warps x (3 row-tiles x 4 n-tiles). K=128, N=256.
#define EMP 132
#define EOP 260
#define EQ_SMEM ((48 * EMP + 48 * EOP) * 4)
__global__ __launch_bounds__(256) void k_equiv()
{
    extern __shared__ float sme[];
    float* smu  = sme;                // [48][EMP]  mu rows
    float* sout = sme + 48 * EMP;     // [48][EOP]  mu_cat rows
    int tid = threadIdx.x;
    int n0 = blockIdx.x * 16;
    int row_base = n0 * 3;

    for (int i = tid; i < 48 * HH; i += 256) {
        int r = i >> 7, c = i & 127;
        int grow = row_base + r;
        smu[r * EMP + c] = (grow < NN * 3) ? g_mumid[grow * HH + c] : 0.f;
    }
    __syncthreads();

    int wid  = tid >> 5;
    int lane = tid & 31;
    int gid  = lane >> 2;
    int tig  = lane & 3;
    int nbase = wid * 32;             // 4 n-tiles of 8 per warp

    float acc[3][4][4];
    #pragma unroll
    for (int r = 0; r < 3; ++r)
        #pragma unroll
        for (int t = 0; t < 4; ++t)
            #pragma unroll
            for (int c = 0; c < 4; ++c) acc[r][t][c] = 0.f;

    #pragma unroll 1
    for (int k0 = 0; k0 < HH; k0 += 16) {
        int kp = k0 >> 1;
        u32 bh[4][2], bl[4][2];
        #pragma unroll
        for (int t = 0; t < 4; ++t) {
            int col = nbase + t * 8 + gid;
            int i0 = (kp + tig) * H2 + col;
            int i1 = (kp + 4 + tig) * H2 + col;
            bh[t][0] = __ldg(&g_vch[i0]);
            bh[t][1] = __ldg(&g_vch[i1]);
            bl[t][0] = __ldg(&g_vcl[i0]);
            bl[t][1] = __ldg(&g_vcl[i1]);
        }
        #pragma unroll
        for (int r = 0; r < 3; ++r) {
            int rb = r * 16;
            float2 f0 = *(const float2*)&smu[(rb + gid)     * EMP + k0 + 2 * tig];
            float2 f1 = *(const float2*)&smu[(rb + gid + 8) * EMP + k0 + 2 * tig];
            float2 f2 = *(const float2*)&smu[(rb + gid)     * EMP + k0 + 8 + 2 * tig];
            float2 f3 = *(const float2*)&smu[(rb + gid + 8) * EMP + k0 + 8 + 2 * tig];
            u32 ah0, al0, ah1, al1, ah2, al2, ah3, al3;
            split_a(f0, ah0, al0); split_a(f1, ah1, al1);
            split_a(f2, ah2, al2); split_a(f3, ah3, al3);
            #pragma unroll
            for (int t = 0; t < 4; ++t) {
                mma_bf16(acc[r][t][0], acc[r][t][1], acc[r][t][2], acc[r][t][3],
                         ah0, ah1, ah2, ah3, bh[t][0], bh[t][1]);
                mma_bf16(acc[r][t][0], acc[r][t][1], acc[r][t][2], acc[r][t][3],
                         al0, al1, al2, al3, bh[t][0], bh[t][1]);
                mma_bf16(acc[r][t][0], acc[r][t][1], acc[r][t][2], acc[r][t][3],
                         ah0, ah1, ah2, ah3, bl[t][0], bl[t][1]);
            }
        }
    }

    #pragma unroll
    for (int r = 0; r < 3; ++r) {
        int row0 = r * 16 + gid;
        int row1 = row0 + 8;
        #pragma unroll
        for (int t = 0; t < 4; ++t) {
            int col = nbase + t * 8 + 2 * tig;
            sout[row0 * EOP + col]     = acc[r][t][0];
            sout[row0 * EOP + col + 1] = acc[r][t][1];
            sout[row1 * EOP + col]     = acc[r][t][2];
            sout[row1 * EOP + col + 1] = acc[r][t][3];
        }
    }
    __syncthreads();

    // reduction: vnorm, inner, muw
    for (int slot = tid; slot < 16 * HH; slot += 256) {
        int r = slot >> 7;        // node within block
        int o = slot & 127;
        int n = n0 + r;
        if (n >= NN) break;
        float v0 = sout[(r * 3 + 0) * EOP + o];
        float v1 = sout[(r * 3 + 1) * EOP + o];
        float v2 = sout[(r * 3 + 2) * EOP + o];
        float w0 = sout[(r * 3 + 0) * EOP + HH + o];
        float w1 = sout[(r * 3 + 1) * EOP + HH + o];
        float w2 = sout[(r * 3 + 2) * EOP + HH + o];
        g_vnorm[n * HH + o] = sqrtf(v0 * v0 + v1 * v1 + v2 * v2 + 1e-8f);
        g_inner[n * HH + o] = v0 * w0 + v1 * w1 + v2 * w2;
        g_muw[n * 3 * HH + o]          = w0;
        g_muw[n * 3 * HH + HH + o]     = w1;
        g_muw[n * 3 * HH + 2 * HH + o] = w2;
    }
}

// ---------------- scalar mix MLP via bf16 split mma + final update ----------------
// 32 nodes/block. sA [32][388] (input 256 cols, later delta 384), sB [32][388] hidden.
#define MXP 388
#define MIX_SMEM ((32 * MXP * 2) * 4)
__global__ __launch_bounds__(256) void k_mix(
    const float* __restrict__ bm1, const float* __restrict__ bm2,
    float* __restrict__ qout, float* __restrict__ muout)
{
    extern __shared__ float smx[];
    float* sA = smx;                  // [32][MXP]
    float* sB = smx + 32 * MXP;       // [32][MXP]
    int tid = threadIdx.x;
    int n0 = blockIdx.x * 32;

    for (int i = tid; i < 32 * H2; i += 256) {
        int r = i >> 8, c = i & 255;
        int n = n0 + r;
        float v = 0.f;
        if (n < NN) v = (c < HH) ? g_qmid[n * HH + c] : g_vnorm[n * HH + (c - HH)];
        sA[r * MXP + c] = v;
    }
    __syncthreads();

    int wid  = tid >> 5;
    int lane = tid & 31;
    int gid  = lane >> 2;
    int tig  = lane & 3;
    int nbase = wid * 48;

    // phase 1: hidden = silu(scalar_input @ Wm1 + bm1), K=256
    {
        float acc[2][6][4];
        #pragma unroll
        for (int r = 0; r < 2; ++r)
            #pragma unroll
            for (int t = 0; t < 6; ++t)
                #pragma unroll
                for (int c = 0; c < 4; ++c) acc[r][t][c] = 0.f;

        #pragma unroll 1
        for (int k0 = 0; k0 < H2; k0 += 16) {
            int kp = k0 >> 1;
            u32 bh[6][2], bl[6][2];
            #pragma unroll
            for (int t = 0; t < 6; ++t) {
                int col = nbase + t * 8 + gid;
                int i0 = (kp + tig) * H3 + col;
                int i1 = (kp + 4 + tig) * H3 + col;
                bh[t][0] = __ldg(&g_m1h[i0]);
                bh[t][1] = __ldg(&g_m1h[i1]);
                bl[t][0] = __ldg(&g_m1l[i0]);
                bl[t][1] = __ldg(&g_m1l[i1]);
            }
            #pragma unroll
            for (int r = 0; r < 2; ++r) {
                int rb = r * 16;
                float2 f0 = *(const float2*)&sA[(rb + gid)     * MXP + k0 + 2 * tig];
                float2 f1 = *(const float2*)&sA[(rb + gid + 8) * MXP + k0 + 2 * tig];
                float2 f2 = *(const float2*)&sA[(rb + gid)     * MXP + k0 + 8 + 2 * tig];
                float2 f3 = *(const float2*)&sA[(rb + gid + 8) * MXP + k0 + 8 + 2 * tig];
                u32 ah0, al0, ah1, al1, ah2, al2, ah3, al3;
                split_a(f0, ah0, al0); split_a(f1, ah1, al1);
                split_a(f2, ah2, al2); split_a(f3, ah3, al3);
                #pragma unroll
                for (int t = 0; t < 6; ++t) {
                    mma_bf16(acc[r][t][0], acc[r][t][1], acc[r][t][2], acc[r][t][3],
                             ah0, ah1, ah2, ah3, bh[t][0], bh[t][1]);
                    mma_bf16(acc[r][t][0], acc[r][t][1], acc[r][t][2], acc[r][t][3],
                             al0, al1, al2, al3, bh[t][0], bh[t][1]);
                    mma_bf16(acc[r][t][0], acc[r][t][1], acc[r][t][2], acc[r][t][3],
                             ah0, ah1, ah2, ah3, bl[t][0], bl[t][1]);
                }
            }
        }
        #pragma unroll
        for (int r = 0; r < 2; ++r) {
            int row0 = r * 16 + gid;
            int row1 = row0 + 8;
            #pragma unroll
            for (int t = 0; t < 6; ++t) {
                int col = nbase + t * 8 + 2 * tig;
                float b0v = __ldg(&bm1[col]);
                float b1v = __ldg(&bm1[col + 1]);
                sB[row0 * MXP + col]     = silu_f(acc[r][t][0] + b0v);
                sB[row0 * MXP + col + 1] = silu_f(acc[r][t][1] + b1v);
                sB[row1 * MXP + col]     = silu_f(acc[r][t][2] + b0v);
                sB[row1 * MXP + col + 1] = silu_f(acc[r][t][3] + b1v);
            }
        }
    }
    __syncthreads();

    // phase 2: delta = hidden @ Wm2 + bm2, K=384 -> store into sA
    {
        float acc[2][6][4];
        #pragma unroll
        for (int r = 0; r < 2; ++r)
            #pragma unroll
            for (int t = 0; t < 6; ++t)
                #pragma unroll
                for (int c = 0; c < 4; ++c) acc[r][t][c] = 0.f;

        #pragma unroll 1
        for (int k0 = 0; k0 < H3; k0 += 16) {
            int kp = k0 >> 1;
            u32 bh[6][2], bl[6][2];
            #pragma unroll
            for (int t = 0; t < 6; ++t) {
                int col = nbase + t * 8 + gid;
                int i0 = (kp + tig) * H3 + col;
                int i1 = (kp + 4 + tig) * H3 + col;
                bh[t][0] = __ldg(&g_m2h[i0]);
                bh[t][1] = __ldg(&g_m2h[i1]);
                bl[t][0] = __ldg(&g_m2l[i0]);
                bl[t][1] = __ldg(&g_m2l[i1]);
            }
            #pragma unroll
            for (int r = 0; r < 2; ++r) {
                int rb = r * 16;
                float2 f0 = *(const float2*)&sB[(rb + gid)     * MXP + k0 + 2 * tig];
                float2 f1 = *(const float2*)&sB[(rb + gid + 8) * MXP + k0 + 2 * tig];
                float2 f2 = *(const float2*)&sB[(rb + gid)     * MXP + k0 + 8 + 2 * tig];
                float2 f3 = *(const float2*)&sB[(rb + gid + 8) * MXP + k0 + 8 + 2 * tig];
                u32 ah0, al0, ah1, al1, ah2, al2, ah3, al3;
                split_a(f0, ah0, al0); split_a(f1, ah1, al1);
                split_a(f2, ah2, al2); split_a(f3, ah3, al3);
                #pragma unroll
                for (int t = 0; t < 6; ++t) {
                    mma_bf16(acc[r][t][0], acc[r][t][1], acc[r][t][2], acc[r][t][3],
                             ah0, ah1, ah2, ah3, bh[t][0], bh[t][1]);
                    mma_bf16(acc[r][t][0], acc[r][t][1], acc[r][t][2], acc[r][t][3],
                             al0, al1, al2, al3, bh[t][0], bh[t][1]);
                    mma_bf16(acc[r][t][0], acc[r][t][1], acc[r][t][2], acc[r][t][3],
                             ah0, ah1, ah2, ah3, bl[t][0], bl[t][1]);
                }
            }
        }
        __syncthreads();   // done reading input from sA
        #pragma unroll
        for (int r = 0; r < 2; ++r) {
            int row0 = r * 16 + gid;
            int row1 = row0 + 8;
            #pragma unroll
            for (int t = 0; t < 6; ++t) {
                int col = nbase + t * 8 + 2 * tig;
                float b0v = __ldg(&bm2[col]);
                float b1v = __ldg(&bm2[col + 1]);
                sA[row0 * MXP + col]     = acc[r][t][0] + b0v;
                sA[row0 * MXP + col + 1] = acc[r][t][1] + b1v;
                sA[row1 * MXP + col]     = acc[r][t][2] + b0v;
                sA[row1 * MXP + col + 1] = acc[r][t][3] + b1v;
            }
        }
    }
    __syncthreads();

    // final update
    for (int slot = tid; slot < 32 * HH; slot += 256) {
        int r = slot >> 7;
        int o = slot & 127;
        int n = n0 + r;
        if (n >= NN) break;
        float dq  = sA[r * MXP + o];
        float dms = sA[r * MXP + HH + o];
        float dqm = sA[r * MXP + 2 * HH + o];
        qout[n * HH + o] = g_qmid[n * HH + o] + dq + dqm * g_inner[n * HH + o];
        #pragma unroll
        for (int d = 0; d < 3; ++d) {
            int idx = n * 3 * HH + d * HH + o;
            muout[idx] = g_mumid[idx] + g_muw[idx] * dms;
        }
    }
}

// ---------------- launch ----------------
extern "C" void kernel_launch(void* const* d_in, const int* in_sizes, int n_in,
                              void* d_out, int out_size)
{
    const float* q   = (const float*)d_in[0];
    const float* mu  = (const float*)d_in[1];
    const int*   ei  = (const int*)d_in[2];
    const float* rbf = (const float*)d_in[3];
    const float* uv  = (const float*)d_in[4];
    const float* cut = (const float*)d_in[5];
    const float* Wi1 = (const float*)d_in[6];
    const float* bi1 = (const float*)d_in[7];
    const float* Wi2 = (const float*)d_in[8];
    const float* bi2 = (const float*)d_in[9];
    const float* Wf1 = (const float*)d_in[10];
    const float* bf1 = (const float*)d_in[11];
    const float* Wf2 = (const float*)d_in[12];
    const float* bf2 = (const float*)d_in[13];
    const float* Wv  = (const float*)d_in[14];
    const float* Wm1 = (const float*)d_in[15];
    const float* bm1 = (const float*)d_in[16];
    const float* Wm2 = (const float*)d_in[17];
    const float* bm2 = (const float*)d_in[18];

    float* qout  = (float*)d_out;
    float* muout = qout + (size_t)NN * HH;

    cudaFuncSetAttribute(k_node_mlp, cudaFuncAttributeMaxDynamicSharedMemorySize, NODE_SMEM);
    cudaFuncSetAttribute(k_equiv,    cudaFuncAttributeMaxDynamicSharedMemorySize, EQ_SMEM);
    cudaFuncSetAttribute(k_mix,      cudaFuncAttributeMaxDynamicSharedMemorySize, MIX_SMEM);

    // CSR build + weight splits
    k_zero<<<(NN + 255) / 256, 256>>>();
    k_count<<<512, 256>>>(ei);
    {
        u32 *p0, *p1;
        cudaGetSymbolAddress((void**)&p0, g_bhp); cudaGetSymbolAddress((void**)&p1, g_blp);
        k_splitw<<<((HH / 2) * H3 + 255) / 256, 256>>>(Wf2, p0, p1, HH / 2, H3);
        cudaGetSymbolAddress((void**)&p0, g_i1h); cudaGetSymbolAddress((void**)&p1, g_i1l);
        k_splitw<<<((HH / 2) * H3 + 255) / 256, 256>>>(Wi1, p0, p1, HH / 2, H3);
        cudaGetSymbolAddress((void**)&p0, g_i2h); cudaGetSymbolAddress((void**)&p1, g_i2l);
        k_splitw<<<((H3 / 2) * H3 + 255) / 256, 256>>>(Wi2, p0, p1, H3 / 2, H3);
        cudaGetSymbolAddress((void**)&p0, g_vch); cudaGetSymbolAddress((void**)&p1, g_vcl);
        k_splitw<<<((HH / 2) * H2 + 255) / 256, 256>>>(Wv, p0, p1, HH / 2, H2);
        cudaGetSymbolAddress((void**)&p0, g_m1h); cudaGetSymbolAddress((void**)&p1, g_m1l);
        k_splitw<<<((H2 / 2) * H3 + 255) / 256, 256>>>(Wm1, p0, p1, H2 / 2, H3);
        cudaGetSymbolAddress((void**)&p0, g_m2h); cudaGetSymbolAddress((void**)&p1, g_m2l);
        k_splitw<<<((H3 / 2) * H3 + 255) / 256, 256>>>(Wm2, p0, p1, H3 / 2, H3);
    }
    k_scan<<<1, 1024>>>();
    k_fill<<<512, 256>>>(ei);

    // dense stages
    k_node_mlp<<<(NN + 31) / 32, 256, NODE_SMEM>>>(q, bi1, bi2);
    k_edge_filter<<<NE / 64, 256>>>(rbf, cut, Wf1, bf1, bf2);

    // message aggregation
    k_aggregate<<<NN, 128>>>(q, mu, ei, uv);

    // mixing
    k_equiv<<<(NN + 15) / 16, 256, EQ_SMEM>>>();
    k_mix<<<(NN + 31) / 32, 256, MIX_SMEM>>>(bm1, bm2, qout, muout);
}